// round 6
// baseline (speedup 1.0000x reference)
#include <cuda_runtime.h>
#include <cuda_bf16.h>
#include <math.h>

// ---------------- problem constants ----------------
#define T_TOK 8192          // 4*2048 tokens
#define DIM   1024          // model dim D
#define FDIM  4096          // expert hidden F
#define NEXP  8
#define TOPK  2
#define TOTAL (T_TOK*TOPK)  // 16384 routed rows (exact invariant)

// GEMM tiling
#define BM 128
#define BN 128
#define BK 8
#define PAD 4
#define BW (BM+PAD)         // 132
#define MAX_TILES (TOTAL/BM + NEXP)   // 136 m-tiles upper bound

// ---------------- device scratch (allocation-free rule: __device__ globals) ----------------
__device__ __align__(16) float g_Xg[(size_t)TOTAL*DIM];    // 64 MB gathered activations
__device__ __align__(16) float g_H [(size_t)TOTAL*FDIM];   // 256 MB SwiGLU hidden
__device__ __align__(16) float g_Og[(size_t)TOTAL*DIM];    // 64 MB per-slot expert output (weighted)
__device__ int   g_tok[TOTAL];
__device__ float g_wgt[TOTAL];
__device__ int   g_slot[TOTAL];       // (t*2+k) -> gathered row p
__device__ int   g_topk_idx[TOTAL];
__device__ float g_topk_w[TOTAL];
__device__ int   g_counts[NEXP];
__device__ int   g_offs[NEXP+1];
__device__ int   g_cursor[NEXP];
__device__ int   g_tile_e[MAX_TILES];
__device__ int   g_tile_r[MAX_TILES];

// ---------------- packed f32x2 FMA (Blackwell FFMA2, PTX-only) ----------------
__device__ __forceinline__ void fma2(unsigned long long& acc, unsigned long long a, unsigned long long b) {
    asm("fma.rn.f32x2 %0, %1, %2, %0;" : "+l"(acc) : "l"(a), "l"(b));
}
__device__ __forceinline__ unsigned long long pack_dup(float v) {
    unsigned long long r; unsigned u = __float_as_uint(v);
    asm("mov.b64 %0, {%1, %1};" : "=l"(r) : "r"(u));
    return r;
}
union U64F2 { unsigned long long u; float2 f; };

// ---------------- K0: zero counts ----------------
__global__ void k_zero() {
    if (threadIdx.x < NEXP) g_counts[threadIdx.x] = 0;
}

// ---------------- K1: gate logits + top2 + softmax (1 warp / token) ----------------
__global__ void k_gate(const float* __restrict__ x, const float* __restrict__ gw) {
    int warp = threadIdx.x >> 5, lane = threadIdx.x & 31;
    int t = blockIdx.x * 8 + warp;
    const float* xr = x + (size_t)t * DIM;
    float acc[NEXP];
    #pragma unroll
    for (int e = 0; e < NEXP; e++) acc[e] = 0.f;
    #pragma unroll 4
    for (int it = 0; it < DIM/32; it++) {
        int d = it*32 + lane;
        float xv = xr[d];
        const float4* g4 = (const float4*)(gw + (size_t)d * NEXP);
        float4 ga = g4[0], gb = g4[1];
        acc[0] += xv*ga.x; acc[1] += xv*ga.y; acc[2] += xv*ga.z; acc[3] += xv*ga.w;
        acc[4] += xv*gb.x; acc[5] += xv*gb.y; acc[6] += xv*gb.z; acc[7] += xv*gb.w;
    }
    #pragma unroll
    for (int e = 0; e < NEXP; e++)
        #pragma unroll
        for (int off = 16; off > 0; off >>= 1)
            acc[e] += __shfl_xor_sync(0xffffffffu, acc[e], off);
    if (lane == 0) {
        float v0 = -INFINITY, v1 = -INFINITY; int i0 = 0, i1 = 0;
        #pragma unroll
        for (int e = 0; e < NEXP; e++) {
            float s = acc[e];
            if (s > v0)      { v1 = v0; i1 = i0; v0 = s; i0 = e; }
            else if (s > v1) { v1 = s;  i1 = e; }
        }
        float e1 = expf(v1 - v0);
        float inv = 1.f / (1.f + e1);
        float w0 = inv, w1 = e1 * inv;
        g_topk_idx[2*t]   = i0; g_topk_w[2*t]   = w0;
        g_topk_idx[2*t+1] = i1; g_topk_w[2*t+1] = w1;
        atomicAdd(&g_counts[i0], 1);
        atomicAdd(&g_counts[i1], 1);
    }
}

// ---------------- K2: scan + tile metadata (serial, trivial) ----------------
__global__ void k_scan() {
    if (threadIdx.x != 0) return;
    int off = 0;
    for (int e = 0; e < NEXP; e++) { g_offs[e] = off; g_cursor[e] = off; off += g_counts[e]; }
    g_offs[NEXP] = off;   // == TOTAL
    int tc = 0;
    for (int e = 0; e < NEXP; e++) {
        int c = g_counts[e];
        for (int r = 0; r < c; r += BM) { g_tile_e[tc] = e; g_tile_r[tc] = g_offs[e] + r; tc++; }
    }
    for (; tc < MAX_TILES; tc++) g_tile_e[tc] = -1;
}

// ---------------- K3: scatter assignments to per-expert segments ----------------
__global__ void k_scatter() {
    int i = blockIdx.x * blockDim.x + threadIdx.x;
    if (i >= TOTAL) return;
    int e = g_topk_idx[i];
    int p = atomicAdd(&g_cursor[e], 1);
    g_tok[p]  = i >> 1;
    g_wgt[p]  = g_topk_w[i];
    g_slot[i] = p;
}

// ---------------- K4: gather x rows into contiguous Xg ----------------
__global__ void k_gather(const float* __restrict__ x) {
    int p = blockIdx.x;
    int t = g_tok[p];
    const float4* src = (const float4*)(x + (size_t)t * DIM);
    float4* dst = (float4*)(g_Xg + (size_t)p * DIM);
    dst[threadIdx.x] = src[threadIdx.x];
}

// ---------------- K5: GEMM1  H = silu(Xg @ w1[e]) * (Xg @ w3[e]) ----------------
__global__ __launch_bounds__(256, 1)
void k_gemm1(const float* __restrict__ w1, const float* __restrict__ w3) {
    int e = g_tile_e[blockIdx.x];
    if (e < 0) return;
    int row0 = g_tile_r[blockIdx.x];
    int row_end = g_offs[e + 1];
    int n0 = blockIdx.y * BN;

    const float* B1 = w1 + (size_t)e * DIM * FDIM;
    const float* B3 = w3 + (size_t)e * DIM * FDIM;

    __shared__ __align__(16) float As [2][BK][BW];
    __shared__ __align__(16) float Bs1[2][BK][BW];
    __shared__ __align__(16) float Bs2[2][BK][BW];

    int tid = threadIdx.x;
    int tmB = (tid >> 4) * 8;        // 0..120
    int tnB = (tid & 15) * 8;        // 0..120

    int aRow = tid >> 1;             // 0..127
    int aCol = (tid & 1) * 4;        // 0/4
    int bRow = tid >> 5;             // 0..7
    int bCol = (tid & 31) * 4;       // 0..124

    int gRow = row0 + aRow; if (gRow > TOTAL - 1) gRow = TOTAL - 1;
    const float* aPtr  = g_Xg + (size_t)gRow * DIM + aCol;
    const float* b1Ptr = B1 + (size_t)bRow * FDIM + n0 + bCol;
    const float* b3Ptr = B3 + (size_t)bRow * FDIM + n0 + bCol;

    // prologue: tile 0
    float4 av  = *(const float4*)aPtr;
    float4 bv1 = *(const float4*)b1Ptr;
    float4 bv3 = *(const float4*)b3Ptr;
    As[0][aCol+0][aRow] = av.x; As[0][aCol+1][aRow] = av.y;
    As[0][aCol+2][aRow] = av.z; As[0][aCol+3][aRow] = av.w;
    *(float4*)&Bs1[0][bRow][bCol] = bv1;
    *(float4*)&Bs2[0][bRow][bCol] = bv3;
    __syncthreads();

    unsigned long long acc1[8][4] = {};
    unsigned long long acc3[8][4] = {};

    const int NK = DIM / BK;  // 128
    for (int kt = 0; kt < NK; kt++) {
        int cur = kt & 1, nxt = cur ^ 1;
        if (kt + 1 < NK) {
            av  = *(const float4*)(aPtr  + (kt + 1) * BK);
            bv1 = *(const float4*)(b1Ptr + (size_t)(kt + 1) * BK * FDIM);
            bv3 = *(const float4*)(b3Ptr + (size_t)(kt + 1) * BK * FDIM);
        }
        #pragma unroll
        for (int k = 0; k < BK; k++) {
            float4 a0 = *(const float4*)&As[cur][k][tmB];
            float4 a1 = *(const float4*)&As[cur][k][tmB + 4];
            ulonglong2 p1a = *(const ulonglong2*)&Bs1[cur][k][tnB];
            ulonglong2 p1b = *(const ulonglong2*)&Bs1[cur][k][tnB + 4];
            ulonglong2 p3a = *(const ulonglong2*)&Bs2[cur][k][tnB];
            ulonglong2 p3b = *(const ulonglong2*)&Bs2[cur][k][tnB + 4];
            unsigned long long bp1[4] = {p1a.x, p1a.y, p1b.x, p1b.y};
            unsigned long long bp3[4] = {p3a.x, p3a.y, p3b.x, p3b.y};
            float avs[8] = {a0.x, a0.y, a0.z, a0.w, a1.x, a1.y, a1.z, a1.w};
            #pragma unroll
            for (int i = 0; i < 8; i++) {
                unsigned long long ap = pack_dup(avs[i]);
                #pragma unroll
                for (int j = 0; j < 4; j++) {
                    fma2(acc1[i][j], ap, bp1[j]);
                    fma2(acc3[i][j], ap, bp3[j]);
                }
            }
        }
        if (kt + 1 < NK) {
            As[nxt][aCol+0][aRow] = av.x; As[nxt][aCol+1][aRow] = av.y;
            As[nxt][aCol+2][aRow] = av.z; As[nxt][aCol+3][aRow] = av.w;
            *(float4*)&Bs1[nxt][bRow][bCol] = bv1;
            *(float4*)&Bs2[nxt][bRow][bCol] = bv3;
        }
        __syncthreads();
    }

    // epilogue: SwiGLU, guarded to this expert's rows only
    #pragma unroll
    for (int i = 0; i < 8; i++) {
        int row = row0 + tmB + i;
        if (row >= row_end) continue;
        float* hr = g_H + (size_t)row * FDIM + n0 + tnB;
        #pragma unroll
        for (int j = 0; j < 4; j++) {
            U64F2 u1; u1.u = acc1[i][j];
            U64F2 u3; u3.u = acc3[i][j];
            float h0 = (u1.f.x / (1.f + expf(-u1.f.x))) * u3.f.x;
            float h1 = (u1.f.y / (1.f + expf(-u1.f.y))) * u3.f.y;
            *(float2*)&hr[2*j] = make_float2(h0, h1);
        }
    }
}

// ---------------- K6: GEMM2  Og = (H @ w2[e]) * route_weight ----------------
__global__ __launch_bounds__(256, 1)
void k_gemm2(const float* __restrict__ w2) {
    int e = g_tile_e[blockIdx.x];
    if (e < 0) return;
    int row0 = g_tile_r[blockIdx.x];
    int row_end = g_offs[e + 1];
    int n0 = blockIdx.y * BN;

    const float* B2 = w2 + (size_t)e * FDIM * DIM;

    __shared__ __align__(16) float As[2][BK][BW];
    __shared__ __align__(16) float Bs[2][BK][BW];

    int tid = threadIdx.x;
    int tmB = (tid >> 4) * 8;
    int tnB = (tid & 15) * 8;

    int aRow = tid >> 1;
    int aCol = (tid & 1) * 4;
    int bRow = tid >> 5;
    int bCol = (tid & 31) * 4;

    int gRow = row0 + aRow; if (gRow > TOTAL - 1) gRow = TOTAL - 1;
    const float* aPtr = g_H + (size_t)gRow * FDIM + aCol;
    const float* bPtr = B2 + (size_t)bRow * DIM + n0 + bCol;

    float4 av = *(const float4*)aPtr;
    float4 bv = *(const float4*)bPtr;
    As[0][aCol+0][aRow] = av.x; As[0][aCol+1][aRow] = av.y;
    As[0][aCol+2][aRow] = av.z; As[0][aCol+3][aRow] = av.w;
    *(float4*)&Bs[0][bRow][bCol] = bv;
    __syncthreads();

    unsigned long long acc[8][4] = {};

    const int NK = FDIM / BK;  // 512
    for (int kt = 0; kt < NK; kt++) {
        int cur = kt & 1, nxt = cur ^ 1;
        if (kt + 1 < NK) {
            av = *(const float4*)(aPtr + (kt + 1) * BK);
            bv = *(const float4*)(bPtr + (size_t)(kt + 1) * BK * DIM);
        }
        #pragma unroll
        for (int k = 0; k < BK; k++) {
            float4 a0 = *(const float4*)&As[cur][k][tmB];
            float4 a1 = *(const float4*)&As[cur][k][tmB + 4];
            ulonglong2 pa = *(const ulonglong2*)&Bs[cur][k][tnB];
            ulonglong2 pb = *(const ulonglong2*)&Bs[cur][k][tnB + 4];
            unsigned long long bp[4] = {pa.x, pa.y, pb.x, pb.y};
            float avs[8] = {a0.x, a0.y, a0.z, a0.w, a1.x, a1.y, a1.z, a1.w};
            #pragma unroll
            for (int i = 0; i < 8; i++) {
                unsigned long long ap = pack_dup(avs[i]);
                #pragma unroll
                for (int j = 0; j < 4; j++) fma2(acc[i][j], ap, bp[j]);
            }
        }
        if (kt + 1 < NK) {
            As[nxt][aCol+0][aRow] = av.x; As[nxt][aCol+1][aRow] = av.y;
            As[nxt][aCol+2][aRow] = av.z; As[nxt][aCol+3][aRow] = av.w;
            *(float4*)&Bs[nxt][bRow][bCol] = bv;
        }
        __syncthreads();
    }

    #pragma unroll
    for (int i = 0; i < 8; i++) {
        int row = row0 + tmB + i;
        if (row >= row_end) continue;
        float wg = g_wgt[row];
        float* orow = g_Og + (size_t)row * DIM + n0 + tnB;
        #pragma unroll
        for (int j = 0; j < 4; j++) {
            U64F2 u; u.u = acc[i][j];
            *(float2*)&orow[2*j] = make_float2(u.f.x * wg, u.f.y * wg);
        }
    }
}

// ---------------- K7: combine — out[t] = Og[slot0] + Og[slot1] (no atomics) ----------------
__global__ void k_combine(float* __restrict__ out) {
    int t = blockIdx.x;
    int s0 = g_slot[2*t], s1 = g_slot[2*t+1];
    float4 a = ((const float4*)(g_Og + (size_t)s0 * DIM))[threadIdx.x];
    float4 b = ((const float4*)(g_Og + (size_t)s1 * DIM))[threadIdx.x];
    float4 o = make_float4(a.x + b.x, a.y + b.y, a.z + b.z, a.w + b.w);
    ((float4*)(out + (size_t)t * DIM))[threadIdx.x] = o;
}

// ---------------- launch ----------------
extern "C" void kernel_launch(void* const* d_in, const int* in_sizes, int n_in,
                              void* d_out, int out_size) {
    const float* x  = (const float*)d_in[0];   // [8192,1024]
    const float* gw = (const float*)d_in[1];   // [1024,8]
    const float* w1 = (const float*)d_in[2];   // [8,1024,4096]
    const float* w2 = (const float*)d_in[3];   // [8,4096,1024]
    const float* w3 = (const float*)d_in[4];   // [8,1024,4096]
    float* out = (float*)d_out;

    k_zero<<<1, 32>>>();
    k_gate<<<T_TOK / 8, 256>>>(x, gw);
    k_scan<<<1, 32>>>();
    k_scatter<<<TOTAL / 256, 256>>>();
    k_gather<<<TOTAL, 256>>>(x);
    dim3 g1(MAX_TILES, FDIM / BN);   // 136 x 32
    k_gemm1<<<g1, 256>>>(w1, w3);
    dim3 g2(MAX_TILES, DIM / BN);    // 136 x 8
    k_gemm2<<<g2, 256>>>(w2);
    k_combine<<<T_TOK, 256>>>(out);
}

// round 11
// speedup vs baseline: 1.8088x; 1.8088x over previous
#include <cuda_runtime.h>
#include <cuda_bf16.h>
#include <math.h>

// ---------------- problem constants ----------------
#define T_TOK 8192
#define DIM   1024
#define FDIM  4096
#define NEXP  8
#define TOTAL (T_TOK*2)               // 16384 routed rows (exact invariant)
#define BM 128
#define MAX_TILES (TOTAL/BM + NEXP)   // 136

// GEMM1 smem: Ah,Al 128x48B + B1h,B1l,B3h,B3l 64x48B = 24576/stage, x2 = 49152 (static max)
#define AROW   48                     // padded row pitch (32B data + 16B pad)
#define ATILE  (128*AROW)             // 6144
#define BTILE  (64*AROW)              // 3072
#define ST1    (2*ATILE + 4*BTILE)    // 24576
#define ST2    (2*ATILE + 2*BTILE)    // 18432

// ---------------- device scratch (~768 MB total) ----------------
__device__ __align__(16) __nv_bfloat16 g_Xh[(size_t)TOTAL*DIM];
__device__ __align__(16) __nv_bfloat16 g_Xl[(size_t)TOTAL*DIM];
__device__ __align__(16) __nv_bfloat16 g_Hh[(size_t)TOTAL*FDIM];
__device__ __align__(16) __nv_bfloat16 g_Hl[(size_t)TOTAL*FDIM];
__device__ __align__(16) __nv_bfloat16 g_W1h[(size_t)NEXP*DIM*FDIM];
__device__ __align__(16) __nv_bfloat16 g_W1l[(size_t)NEXP*DIM*FDIM];
__device__ __align__(16) __nv_bfloat16 g_W3h[(size_t)NEXP*DIM*FDIM];
__device__ __align__(16) __nv_bfloat16 g_W3l[(size_t)NEXP*DIM*FDIM];
__device__ __align__(16) __nv_bfloat16 g_W2h[(size_t)NEXP*FDIM*DIM];
__device__ __align__(16) __nv_bfloat16 g_W2l[(size_t)NEXP*FDIM*DIM];
__device__ __align__(16) float g_Og[(size_t)TOTAL*DIM];
__device__ int   g_tok[TOTAL];
__device__ float g_wgt[TOTAL];
__device__ int   g_slot[TOTAL];
__device__ int   g_topk_idx[TOTAL];
__device__ float g_topk_w[TOTAL];
__device__ int   g_counts[NEXP];
__device__ int   g_offs[NEXP+1];
__device__ int   g_cursor[NEXP];
__device__ int   g_tile_e[MAX_TILES];
__device__ int   g_tile_r[MAX_TILES];

// ---------------- PTX helpers (sm_80-class only) ----------------
__device__ __forceinline__ unsigned smem_u32(const void* p) {
    unsigned a;
    asm("{ .reg .u64 t; cvta.to.shared.u64 t, %1; cvt.u32.u64 %0, t; }" : "=r"(a) : "l"(p));
    return a;
}
__device__ __forceinline__ void ldsm4(unsigned r[4], unsigned addr) {
    asm volatile("ldmatrix.sync.aligned.m8n8.x4.shared.b16 {%0,%1,%2,%3}, [%4];"
                 : "=r"(r[0]), "=r"(r[1]), "=r"(r[2]), "=r"(r[3]) : "r"(addr));
}
__device__ __forceinline__ void mma16816(float d[4], const unsigned a[4], unsigned b0, unsigned b1) {
    asm volatile("mma.sync.aligned.m16n8k16.row.col.f32.bf16.bf16.f32 "
                 "{%0,%1,%2,%3}, {%4,%5,%6,%7}, {%8,%9}, {%0,%1,%2,%3};"
                 : "+f"(d[0]), "+f"(d[1]), "+f"(d[2]), "+f"(d[3])
                 : "r"(a[0]), "r"(a[1]), "r"(a[2]), "r"(a[3]), "r"(b0), "r"(b1));
}

// ---------------- routing kernels (all R6-proven) ----------------
__global__ void k_zero() { if (threadIdx.x < NEXP) g_counts[threadIdx.x] = 0; }

__global__ void k_gate(const float* __restrict__ x, const float* __restrict__ gw) {
    int warp = threadIdx.x >> 5, lane = threadIdx.x & 31;
    int t = blockIdx.x * 8 + warp;
    const float* xr = x + (size_t)t * DIM;
    float acc[NEXP];
    #pragma unroll
    for (int e = 0; e < NEXP; e++) acc[e] = 0.f;
    #pragma unroll 4
    for (int it = 0; it < DIM/32; it++) {
        int d = it*32 + lane;
        float xv = xr[d];
        const float4* g4 = (const float4*)(gw + (size_t)d * NEXP);
        float4 ga = g4[0], gb = g4[1];
        acc[0] += xv*ga.x; acc[1] += xv*ga.y; acc[2] += xv*ga.z; acc[3] += xv*ga.w;
        acc[4] += xv*gb.x; acc[5] += xv*gb.y; acc[6] += xv*gb.z; acc[7] += xv*gb.w;
    }
    #pragma unroll
    for (int e = 0; e < NEXP; e++)
        #pragma unroll
        for (int off = 16; off > 0; off >>= 1)
            acc[e] += __shfl_xor_sync(0xffffffffu, acc[e], off);
    if (lane == 0) {
        float v0 = -INFINITY, v1 = -INFINITY; int i0 = 0, i1 = 0;
        #pragma unroll
        for (int e = 0; e < NEXP; e++) {
            float s = acc[e];
            if (s > v0)      { v1 = v0; i1 = i0; v0 = s; i0 = e; }
            else if (s > v1) { v1 = s;  i1 = e; }
        }
        float e1 = expf(v1 - v0);
        float inv = 1.f / (1.f + e1);
        g_topk_idx[2*t]   = i0; g_topk_w[2*t]   = inv;
        g_topk_idx[2*t+1] = i1; g_topk_w[2*t+1] = e1 * inv;
        atomicAdd(&g_counts[i0], 1);
        atomicAdd(&g_counts[i1], 1);
    }
}

__global__ void k_scan() {
    if (threadIdx.x != 0) return;
    int off = 0;
    for (int e = 0; e < NEXP; e++) { g_offs[e] = off; g_cursor[e] = off; off += g_counts[e]; }
    g_offs[NEXP] = off;
    int tc = 0;
    for (int e = 0; e < NEXP; e++)
        for (int r = 0; r < g_counts[e]; r += BM) { g_tile_e[tc] = e; g_tile_r[tc] = g_offs[e] + r; tc++; }
    for (; tc < MAX_TILES; tc++) g_tile_e[tc] = -1;
}

__global__ void k_scatter() {
    int i = blockIdx.x * blockDim.x + threadIdx.x;
    if (i >= TOTAL) return;
    int e = g_topk_idx[i];
    int p = atomicAdd(&g_cursor[e], 1);
    g_tok[p] = i >> 1; g_wgt[p] = g_topk_w[i]; g_slot[i] = p;
}

__global__ void k_gather(const float* __restrict__ x) {
    int p = blockIdx.x, t = g_tok[p];
    float4 v = ((const float4*)(x + (size_t)t * DIM))[threadIdx.x];
    float f[4] = {v.x, v.y, v.z, v.w};
    unsigned hs[4], ls[4];
    #pragma unroll
    for (int i = 0; i < 4; i++) {
        __nv_bfloat16 h = __float2bfloat16(f[i]);
        float lo = f[i] - __bfloat162float(h);
        hs[i] = __bfloat16_as_ushort(h);
        ls[i] = __bfloat16_as_ushort(__float2bfloat16(lo));
    }
    ((uint2*)(g_Xh + (size_t)p * DIM))[threadIdx.x] = make_uint2(hs[0]|(hs[1]<<16), hs[2]|(hs[3]<<16));
    ((uint2*)(g_Xl + (size_t)p * DIM))[threadIdx.x] = make_uint2(ls[0]|(ls[1]<<16), ls[2]|(ls[3]<<16));
}

// transpose + split weights: W[R][C] fp32 -> [C][R] bf16 hi/lo (K=R contiguous).
// CRITICAL FIX vs R8-R10: output arrays selected INSIDE device code (sel), never
// passed as __device__-symbol kernel args from host (host shadow + GB300 ATS
// silently redirected those writes to host memory, leaving device arrays zero).
__global__ void k_wsplit(const float* __restrict__ W, int sel, int R, int C) {
    __nv_bfloat16 *oh, *ol;
    if      (sel == 0) { oh = g_W1h; ol = g_W1l; }
    else if (sel == 1) { oh = g_W3h; ol = g_W3l; }
    else               { oh = g_W2h; ol = g_W2l; }
    __shared__ float tb[32][33];
    const float* Wb = W + (size_t)blockIdx.z * R * C;
    size_t ob = (size_t)blockIdx.z * R * C;
    int tx = threadIdx.x, ty = threadIdx.y;
    #pragma unroll
    for (int i = 0; i < 4; i++) {
        int r = blockIdx.y*32 + ty + i*8;
        tb[ty + i*8][tx] = Wb[(size_t)r * C + blockIdx.x*32 + tx];
    }
    __syncthreads();
    int rr = blockIdx.y*32 + tx;
    #pragma unroll
    for (int i = 0; i < 4; i++) {
        int cc = blockIdx.x*32 + ty + i*8;
        float v = tb[tx][ty + i*8];
        __nv_bfloat16 h = __float2bfloat16(v);
        float lo = v - __bfloat162float(h);
        size_t o = ob + (size_t)cc * R + rr;
        oh[o] = h; ol[o] = __float2bfloat16(lo);
    }
}

// ---------------- GEMM1 (fused SwiGLU): H = silu(X@W1)*(X@W3), split-3 bf16 ----------------
// CTA 128(M) x 64(N), BK=16, 256 threads, 8 warps (2M x 4N), warp tile 64x16.
__global__ __launch_bounds__(256) void k_gemm1() {
    int e = g_tile_e[blockIdx.y];
    if (e < 0) return;
    int row0 = g_tile_r[blockIdx.y];
    int row_end = g_offs[e + 1];
    int ncol = blockIdx.x * 64;

    __shared__ __align__(16) char sm[2*ST1];
    unsigned sbase = smem_u32(sm);
    int tid = threadIdx.x, lane = tid & 31, wid = tid >> 5;

    // ---- load mapping: A (128 rows x 2 vecs), B (4 tiles x 64 rows x 2 vecs, 2 slots/thread)
    int rowA = tid >> 1, vecA = tid & 1;
    int ar = row0 + rowA; if (ar > TOTAL-1) ar = TOTAL-1;
    const __nv_bfloat16* gAh = g_Xh + (size_t)ar*DIM + vecA*8;
    const __nv_bfloat16* gAl = g_Xl + (size_t)ar*DIM + vecA*8;
    unsigned soA = (unsigned)rowA*AROW + vecA*16;

    size_t eoff = (size_t)e*DIM*FDIM + (size_t)ncol*DIM;
    const __nv_bfloat16* pB[4] = { g_W1h+eoff, g_W1l+eoff, g_W3h+eoff, g_W3l+eoff };
    int q1 = tid >> 7, i1 = tid & 127;            // slot 1: tiles 0,1
    int q2 = (tid+256) >> 7, i2 = tid & 127;      // slot 2: tiles 2,3
    int rB1 = i1 >> 1, vB1 = i1 & 1;
    int rB2 = i2 >> 1, vB2 = i2 & 1;
    const __nv_bfloat16* gB1 = pB[q1] + (size_t)rB1*DIM + vB1*8;
    const __nv_bfloat16* gB2 = pB[q2] + (size_t)rB2*DIM + vB2*8;
    unsigned soB1 = 2*ATILE + q1*BTILE + (unsigned)rB1*AROW + vB1*16;
    unsigned soB2 = 2*ATILE + q2*BTILE + (unsigned)rB2*AROW + vB2*16;

    // ---- compute mapping
    int m0 = (wid & 1) * 64, nw = (wid >> 1) * 16;
    unsigned aoff = (unsigned)(m0 + (lane & 15))*AROW + (lane >> 4)*16;
    unsigned boff = (unsigned)(nw + (lane & 15))*AROW + (lane >> 4)*16;

    float acc1[4][2][4] = {}, acc3[4][2][4] = {};

    // stage 0 direct
    *(uint4*)(sm + soA)          = *(const uint4*)gAh;
    *(uint4*)(sm + ATILE + soA)  = *(const uint4*)gAl;
    *(uint4*)(sm + soB1)         = *(const uint4*)gB1;
    *(uint4*)(sm + soB2)         = *(const uint4*)gB2;
    __syncthreads();

    const int NKT = DIM / 16;   // 64
    for (int kt = 0; kt < NKT; kt++) {
        int cur = kt & 1;
        uint4 pa0, pa1, pb1, pb2;
        if (kt + 1 < NKT) {
            int ko = (kt + 1) * 16;
            pa0 = *(const uint4*)(gAh + ko);
            pa1 = *(const uint4*)(gAl + ko);
            pb1 = *(const uint4*)(gB1 + ko);
            pb2 = *(const uint4*)(gB2 + ko);
        }
        unsigned st = sbase + cur*ST1;
        unsigned ah[4][4], al[4][4];
        #pragma unroll
        for (int mt = 0; mt < 4; mt++) {
            ldsm4(ah[mt], st + aoff + mt*(16*AROW));
            ldsm4(al[mt], st + ATILE + aoff + mt*(16*AROW));
        }
        unsigned t1h[4], t1l[4], t3h[4], t3l[4];
        ldsm4(t1h, st + 2*ATILE + 0*BTILE + boff);
        ldsm4(t1l, st + 2*ATILE + 1*BTILE + boff);
        ldsm4(t3h, st + 2*ATILE + 2*BTILE + boff);
        ldsm4(t3l, st + 2*ATILE + 3*BTILE + boff);
        #pragma unroll
        for (int mt = 0; mt < 4; mt++)
            #pragma unroll
            for (int nt = 0; nt < 2; nt++) {
                mma16816(acc1[mt][nt], ah[mt], t1h[nt], t1h[nt+2]);
                mma16816(acc1[mt][nt], ah[mt], t1l[nt], t1l[nt+2]);
                mma16816(acc1[mt][nt], al[mt], t1h[nt], t1h[nt+2]);
                mma16816(acc3[mt][nt], ah[mt], t3h[nt], t3h[nt+2]);
                mma16816(acc3[mt][nt], ah[mt], t3l[nt], t3l[nt+2]);
                mma16816(acc3[mt][nt], al[mt], t3h[nt], t3h[nt+2]);
            }
        if (kt + 1 < NKT) {
            char* nb = sm + (cur^1)*ST1;
            *(uint4*)(nb + soA)         = pa0;
            *(uint4*)(nb + ATILE + soA) = pa1;
            *(uint4*)(nb + soB1)        = pb1;
            *(uint4*)(nb + soB2)        = pb2;
        }
        __syncthreads();
    }

    // epilogue: SwiGLU -> Hh/Hl
    #pragma unroll
    for (int mt = 0; mt < 4; mt++) {
        int r = row0 + m0 + mt*16 + (lane >> 2);
        #pragma unroll
        for (int nt = 0; nt < 2; nt++) {
            int col = ncol + nw + nt*8 + (lane & 3)*2;
            #pragma unroll
            for (int half = 0; half < 2; half++) {
                int rr = r + half*8;
                if (rr >= row_end) continue;
                float a0 = acc1[mt][nt][2*half], a1 = acc1[mt][nt][2*half+1];
                float c0 = acc3[mt][nt][2*half], c1 = acc3[mt][nt][2*half+1];
                float h0 = a0 / (1.f + __expf(-a0)) * c0;
                float h1 = a1 / (1.f + __expf(-a1)) * c1;
                __nv_bfloat16 b0 = __float2bfloat16(h0), b1 = __float2bfloat16(h1);
                float l0 = h0 - __bfloat162float(b0), l1 = h1 - __bfloat162float(b1);
                unsigned hv = (unsigned)__bfloat16_as_ushort(b0) | ((unsigned)__bfloat16_as_ushort(b1) << 16);
                unsigned lv = (unsigned)__bfloat16_as_ushort(__float2bfloat16(l0))
                            | ((unsigned)__bfloat16_as_ushort(__float2bfloat16(l1)) << 16);
                *(unsigned*)(g_Hh + (size_t)rr*FDIM + col) = hv;
                *(unsigned*)(g_Hl + (size_t)rr*FDIM + col) = lv;
            }
        }
    }
}

// ---------------- GEMM2: Og = (H @ W2) * route_weight ----------------
__global__ __launch_bounds__(256) void k_gemm2() {
    int e = g_tile_e[blockIdx.y];
    if (e < 0) return;
    int row0 = g_tile_r[blockIdx.y];
    int row_end = g_offs[e + 1];
    int ncol = blockIdx.x * 64;

    __shared__ __align__(16) char sm[2*ST2];
    unsigned sbase = smem_u32(sm);
    int tid = threadIdx.x, lane = tid & 31, wid = tid >> 5;

    int rowA = tid >> 1, vecA = tid & 1;
    int ar = row0 + rowA; if (ar > TOTAL-1) ar = TOTAL-1;
    const __nv_bfloat16* gAh = g_Hh + (size_t)ar*FDIM + vecA*8;
    const __nv_bfloat16* gAl = g_Hl + (size_t)ar*FDIM + vecA*8;
    unsigned soA = (unsigned)rowA*AROW + vecA*16;

    size_t eoff = (size_t)e*FDIM*DIM + (size_t)ncol*FDIM;
    int q = tid >> 7, iB = tid & 127;       // 2 tiles x 128 slots, 1 slot/thread
    int rB = iB >> 1, vB = iB & 1;
    const __nv_bfloat16* gB = (q == 0 ? g_W2h : g_W2l) + eoff + (size_t)rB*FDIM + vB*8;
    unsigned soB = 2*ATILE + q*BTILE + (unsigned)rB*AROW + vB*16;

    int m0 = (wid & 1) * 64, nw = (wid >> 1) * 16;
    unsigned aoff = (unsigned)(m0 + (lane & 15))*AROW + (lane >> 4)*16;
    unsigned boff = (unsigned)(nw + (lane & 15))*AROW + (lane >> 4)*16;

    float acc[4][2][4] = {};

    *(uint4*)(sm + soA)         = *(const uint4*)gAh;
    *(uint4*)(sm + ATILE + soA) = *(const uint4*)gAl;
    *(uint4*)(sm + soB)         = *(const uint4*)gB;
    __syncthreads();

    const int NKT = FDIM / 16;  // 256
    for (int kt = 0; kt < NKT; kt++) {
        int cur = kt & 1;
        uint4 pa0, pa1, pb;
        if (kt + 1 < NKT) {
            int ko = (kt + 1) * 16;
            pa0 = *(const uint4*)(gAh + ko);
            pa1 = *(const uint4*)(gAl + ko);
            pb  = *(const uint4*)(gB + ko);
        }
        unsigned st = sbase + cur*ST2;
        unsigned ah[4][4], al[4][4];
        #pragma unroll
        for (int mt = 0; mt < 4; mt++) {
            ldsm4(ah[mt], st + aoff + mt*(16*AROW));
            ldsm4(al[mt], st + ATILE + aoff + mt*(16*AROW));
        }
        unsigned tbh[4], tbl[4];
        ldsm4(tbh, st + 2*ATILE + 0*BTILE + boff);
        ldsm4(tbl, st + 2*ATILE + 1*BTILE + boff);
        #pragma unroll
        for (int mt = 0; mt < 4; mt++)
            #pragma unroll
            for (int nt = 0; nt < 2; nt++) {
                mma16816(acc[mt][nt], ah[mt], tbh[nt], tbh[nt+2]);
                mma16816(acc[mt][nt], ah[mt], tbl[nt], tbl[nt+2]);
                mma16816(acc[mt][nt], al[mt], tbh[nt], tbh[nt+2]);
            }
        if (kt + 1 < NKT) {
            char* nb = sm + (cur^1)*ST2;
            *(uint4*)(nb + soA)         = pa0;
            *(uint4*)(nb + ATILE + soA) = pa1;
            *(uint4*)(nb + soB)         = pb;
        }
        __syncthreads();
    }

    #pragma unroll
    for (int mt = 0; mt < 4; mt++) {
        int r = row0 + m0 + mt*16 + (lane >> 2);
        #pragma unroll
        for (int nt = 0; nt < 2; nt++) {
            int col = ncol + nw + nt*8 + (lane & 3)*2;
            #pragma unroll
            for (int half = 0; half < 2; half++) {
                int rr = r + half*8;
                if (rr >= row_end) continue;
                float wg = g_wgt[rr];
                *(float2*)(g_Og + (size_t)rr*DIM + col) =
                    make_float2(acc[mt][nt][2*half]*wg, acc[mt][nt][2*half+1]*wg);
            }
        }
    }
}

// ---------------- combine ----------------
__global__ void k_combine(float* __restrict__ out) {
    int t = blockIdx.x;
    int s0 = g_slot[2*t], s1 = g_slot[2*t+1];
    float4 a = ((const float4*)(g_Og + (size_t)s0 * DIM))[threadIdx.x];
    float4 b = ((const float4*)(g_Og + (size_t)s1 * DIM))[threadIdx.x];
    ((float4*)(out + (size_t)t * DIM))[threadIdx.x] =
        make_float4(a.x + b.x, a.y + b.y, a.z + b.z, a.w + b.w);
}

// ---------------- launch ----------------
extern "C" void kernel_launch(void* const* d_in, const int* in_sizes, int n_in,
                              void* d_out, int out_size) {
    const float* x  = (const float*)d_in[0];
    const float* gw = (const float*)d_in[1];
    const float* w1 = (const float*)d_in[2];
    const float* w2 = (const float*)d_in[3];
    const float* w3 = (const float*)d_in[4];
    float* out = (float*)d_out;

    k_zero<<<1, 32>>>();
    k_gate<<<T_TOK / 8, 256>>>(x, gw);
    k_scan<<<1, 32>>>();
    k_scatter<<<TOTAL / 256, 256>>>();
    k_gather<<<TOTAL, 256>>>(x);
    k_wsplit<<<dim3(FDIM/32, DIM/32, NEXP), dim3(32, 8)>>>(w1, 0, DIM, FDIM);
    k_wsplit<<<dim3(FDIM/32, DIM/32, NEXP), dim3(32, 8)>>>(w3, 1, DIM, FDIM);
    k_wsplit<<<dim3(DIM/32, FDIM/32, NEXP), dim3(32, 8)>>>(w2, 2, FDIM, DIM);
    k_gemm1<<<dim3(FDIM/64, MAX_TILES), 256>>>();    // 64 x 136
    k_gemm2<<<dim3(DIM/64,  MAX_TILES), 256>>>();    // 16 x 136
    k_combine<<<T_TOK, 256>>>(out);
}

// round 14
// speedup vs baseline: 2.0474x; 1.1319x over previous
#include <cuda_runtime.h>
#include <cuda_bf16.h>
#include <math.h>

// ---------------- problem constants ----------------
#define T_TOK 8192
#define DIM   1024
#define FDIM  4096
#define NEXP  8
#define TOTAL (T_TOK*2)               // 16384 routed rows (exact invariant)
#define BM 128
#define MAX_TILES (TOTAL/BM + NEXP)   // 136

// 32B-pitch swizzled tiles, BK=16, 3-stage cp.async
// GEMM1 stage: Ah,Al 128x32 + B1h,B1l,B3h,B3l 64x32 = 16384 ; x3 = 49152 (static max)
// GEMM2 stage: Ah,Al 128x32 + Bh,Bl 64x32 = 12288 ; x3 = 36864
#define ST1 16384
#define ST2 12288

// ---------------- device scratch (~768 MB total) ----------------
__device__ __align__(16) __nv_bfloat16 g_Xh[(size_t)TOTAL*DIM];
__device__ __align__(16) __nv_bfloat16 g_Xl[(size_t)TOTAL*DIM];
__device__ __align__(16) __nv_bfloat16 g_Hh[(size_t)TOTAL*FDIM];
__device__ __align__(16) __nv_bfloat16 g_Hl[(size_t)TOTAL*FDIM];
__device__ __align__(16) __nv_bfloat16 g_W1h[(size_t)NEXP*DIM*FDIM];
__device__ __align__(16) __nv_bfloat16 g_W1l[(size_t)NEXP*DIM*FDIM];
__device__ __align__(16) __nv_bfloat16 g_W3h[(size_t)NEXP*DIM*FDIM];
__device__ __align__(16) __nv_bfloat16 g_W3l[(size_t)NEXP*DIM*FDIM];
__device__ __align__(16) __nv_bfloat16 g_W2h[(size_t)NEXP*FDIM*DIM];
__device__ __align__(16) __nv_bfloat16 g_W2l[(size_t)NEXP*FDIM*DIM];
__device__ __align__(16) float g_Og[(size_t)TOTAL*DIM];
__device__ int   g_tok[TOTAL];
__device__ float g_wgt[TOTAL];
__device__ int   g_slot[TOTAL];
__device__ int   g_topk_idx[TOTAL];
__device__ float g_topk_w[TOTAL];
__device__ int   g_counts[NEXP];
__device__ int   g_offs[NEXP+1];
__device__ int   g_cursor[NEXP];
__device__ int   g_tile_e[MAX_TILES];
__device__ int   g_tile_r[MAX_TILES];

// ---------------- PTX helpers (sm_80-class only) ----------------
__device__ __forceinline__ unsigned smem_u32(const void* p) {
    unsigned a;
    asm("{ .reg .u64 t; cvta.to.shared.u64 t, %1; cvt.u32.u64 %0, t; }" : "=r"(a) : "l"(p));
    return a;
}
__device__ __forceinline__ void cp16(unsigned dst, const void* src) {
    asm volatile("cp.async.cg.shared.global [%0], [%1], 16;" :: "r"(dst), "l"(src) : "memory");
}
#define CP_COMMIT() asm volatile("cp.async.commit_group;" ::: "memory")
#define CP_WAIT1()  asm volatile("cp.async.wait_group 1;" ::: "memory")
#define CP_WAIT0()  asm volatile("cp.async.wait_group 0;" ::: "memory")

// 32B-pitch tile swizzle: row r, 16B-vec v(0/1) -> conflict-free for ldsm + stores
// quad(r,v) = (2r + (v ^ (r>>2))) mod 8 hits all 8 bank-quads per ldsm phase.
#define SWZOFF(r, v) ((unsigned)(r)*32u + (((unsigned)((v) ^ ((r)>>2)) & 1u)*16u))

__device__ __forceinline__ void ldsm4(unsigned r[4], unsigned addr) {
    asm volatile("ldmatrix.sync.aligned.m8n8.x4.shared.b16 {%0,%1,%2,%3}, [%4];"
                 : "=r"(r[0]), "=r"(r[1]), "=r"(r[2]), "=r"(r[3]) : "r"(addr));
}
__device__ __forceinline__ void mma16816(float d[4], const unsigned a[4], unsigned b0, unsigned b1) {
    asm volatile("mma.sync.aligned.m16n8k16.row.col.f32.bf16.bf16.f32 "
                 "{%0,%1,%2,%3}, {%4,%5,%6,%7}, {%8,%9}, {%0,%1,%2,%3};"
                 : "+f"(d[0]), "+f"(d[1]), "+f"(d[2]), "+f"(d[3])
                 : "r"(a[0]), "r"(a[1]), "r"(a[2]), "r"(a[3]), "r"(b0), "r"(b1));
}

// ---------------- routing kernels (proven) ----------------
__global__ void k_zero() { if (threadIdx.x < NEXP) g_counts[threadIdx.x] = 0; }

__global__ void k_gate(const float* __restrict__ x, const float* __restrict__ gw) {
    int warp = threadIdx.x >> 5, lane = threadIdx.x & 31;
    int t = blockIdx.x * 8 + warp;
    const float* xr = x + (size_t)t * DIM;
    float acc[NEXP];
    #pragma unroll
    for (int e = 0; e < NEXP; e++) acc[e] = 0.f;
    #pragma unroll 4
    for (int it = 0; it < DIM/32; it++) {
        int d = it*32 + lane;
        float xv = xr[d];
        const float4* g4 = (const float4*)(gw + (size_t)d * NEXP);
        float4 ga = g4[0], gb = g4[1];
        acc[0] += xv*ga.x; acc[1] += xv*ga.y; acc[2] += xv*ga.z; acc[3] += xv*ga.w;
        acc[4] += xv*gb.x; acc[5] += xv*gb.y; acc[6] += xv*gb.z; acc[7] += xv*gb.w;
    }
    #pragma unroll
    for (int e = 0; e < NEXP; e++)
        #pragma unroll
        for (int off = 16; off > 0; off >>= 1)
            acc[e] += __shfl_xor_sync(0xffffffffu, acc[e], off);
    if (lane == 0) {
        float v0 = -INFINITY, v1 = -INFINITY; int i0 = 0, i1 = 0;
        #pragma unroll
        for (int e = 0; e < NEXP; e++) {
            float s = acc[e];
            if (s > v0)      { v1 = v0; i1 = i0; v0 = s; i0 = e; }
            else if (s > v1) { v1 = s;  i1 = e; }
        }
        float e1 = expf(v1 - v0);
        float inv = 1.f / (1.f + e1);
        g_topk_idx[2*t]   = i0; g_topk_w[2*t]   = inv;
        g_topk_idx[2*t+1] = i1; g_topk_w[2*t+1] = e1 * inv;
        atomicAdd(&g_counts[i0], 1);
        atomicAdd(&g_counts[i1], 1);
    }
}

__global__ void k_scan() {
    if (threadIdx.x != 0) return;
    int off = 0;
    for (int e = 0; e < NEXP; e++) { g_offs[e] = off; g_cursor[e] = off; off += g_counts[e]; }
    g_offs[NEXP] = off;
    int tc = 0;
    for (int e = 0; e < NEXP; e++)
        for (int r = 0; r < g_counts[e]; r += BM) { g_tile_e[tc] = e; g_tile_r[tc] = g_offs[e] + r; tc++; }
    for (; tc < MAX_TILES; tc++) g_tile_e[tc] = -1;
}

__global__ void k_scatter() {
    int i = blockIdx.x * blockDim.x + threadIdx.x;
    if (i >= TOTAL) return;
    int e = g_topk_idx[i];
    int p = atomicAdd(&g_cursor[e], 1);
    g_tok[p] = i >> 1; g_wgt[p] = g_topk_w[i]; g_slot[i] = p;
}

__global__ void k_gather(const float* __restrict__ x) {
    int p = blockIdx.x, t = g_tok[p];
    float4 v = ((const float4*)(x + (size_t)t * DIM))[threadIdx.x];
    float f[4] = {v.x, v.y, v.z, v.w};
    unsigned hs[4], ls[4];
    #pragma unroll
    for (int i = 0; i < 4; i++) {
        __nv_bfloat16 h = __float2bfloat16(f[i]);
        float lo = f[i] - __bfloat162float(h);
        hs[i] = __bfloat16_as_ushort(h);
        ls[i] = __bfloat16_as_ushort(__float2bfloat16(lo));
    }
    ((uint2*)(g_Xh + (size_t)p * DIM))[threadIdx.x] = make_uint2(hs[0]|(hs[1]<<16), hs[2]|(hs[3]<<16));
    ((uint2*)(g_Xl + (size_t)p * DIM))[threadIdx.x] = make_uint2(ls[0]|(ls[1]<<16), ls[2]|(ls[3]<<16));
}

// transpose + split weights; outputs selected INSIDE device code (ATS-bug fix, R11-proven)
__global__ void k_wsplit(const float* __restrict__ W, int sel, int R, int C) {
    __nv_bfloat16 *oh, *ol;
    if      (sel == 0) { oh = g_W1h; ol = g_W1l; }
    else if (sel == 1) { oh = g_W3h; ol = g_W3l; }
    else               { oh = g_W2h; ol = g_W2l; }
    __shared__ float tb[32][33];
    const float* Wb = W + (size_t)blockIdx.z * R * C;
    size_t ob = (size_t)blockIdx.z * R * C;
    int tx = threadIdx.x, ty = threadIdx.y;
    #pragma unroll
    for (int i = 0; i < 4; i++) {
        int r = blockIdx.y*32 + ty + i*8;
        tb[ty + i*8][tx] = Wb[(size_t)r * C + blockIdx.x*32 + tx];
    }
    __syncthreads();
    int rr = blockIdx.y*32 + tx;
    #pragma unroll
    for (int i = 0; i < 4; i++) {
        int cc = blockIdx.x*32 + ty + i*8;
        float v = tb[tx][ty + i*8];
        __nv_bfloat16 h = __float2bfloat16(v);
        float lo = v - __bfloat162float(h);
        size_t o = ob + (size_t)cc * R + rr;
        oh[o] = h; ol[o] = __float2bfloat16(lo);
    }
}

// ---------------- GEMM1 (fused SwiGLU): H = silu(X@W1)*(X@W3), split-3 bf16 ----------------
// CTA 128(M) x 64(N), BK=16, 256 thr, 8 warps (2M x 4N), warp 64x16. 3-stage cp.async.
__global__ __launch_bounds__(256, 2) void k_gemm1() {
    int e = g_tile_e[blockIdx.y];
    if (e < 0) return;
    int row0 = g_tile_r[blockIdx.y];
    int row_end = g_offs[e + 1];
    int ncol = blockIdx.x * 64;

    __shared__ __align__(128) char sm[3*ST1];
    unsigned sbase = smem_u32(sm);
    int tid = threadIdx.x, lane = tid & 31, wid = tid >> 5;

    // ---- cp.async mapping: A 2x(128rx2v), B 4 tiles x (64rx2v); 4 vec/thread/stage
    int rowA = tid >> 1, vecA = tid & 1;
    int ar = row0 + rowA; if (ar > TOTAL-1) ar = TOTAL-1;
    const __nv_bfloat16* gAh = g_Xh + (size_t)ar*DIM + vecA*8;
    const __nv_bfloat16* gAl = g_Xl + (size_t)ar*DIM + vecA*8;
    unsigned sA = SWZOFF(rowA, vecA);

    size_t eoff = (size_t)e*DIM*FDIM + (size_t)ncol*DIM;
    const __nv_bfloat16* pB[4] = { g_W1h+eoff, g_W1l+eoff, g_W3h+eoff, g_W3l+eoff };
    int q1 = tid >> 7;                       // tiles 0,1
    int i1 = tid & 127, rB1 = i1 >> 1, vB1 = i1 & 1;
    const __nv_bfloat16* gB1 = pB[q1]     + (size_t)rB1*DIM + vB1*8;
    const __nv_bfloat16* gB2 = pB[2 + q1] + (size_t)rB1*DIM + vB1*8;   // tiles 2,3
    unsigned sB1 = 8192  + q1*2048 + SWZOFF(rB1, vB1);
    unsigned sB2 = 12288 + q1*2048 + SWZOFF(rB1, vB1);

    auto load_stage = [&](int kt) {
        unsigned st = sbase + (kt % 3)*ST1;
        int ko = kt * 16;
        cp16(st + sA,        gAh + ko);
        cp16(st + 4096 + sA, gAl + ko);
        cp16(st + sB1,       gB1 + ko);
        cp16(st + sB2,       gB2 + ko);
        CP_COMMIT();
    };

    // ---- compute mapping
    int m0 = (wid & 1) * 64, nw = (wid >> 1) * 16;
    unsigned aoff = SWZOFF(m0 + (lane & 15), lane >> 4);   // mt*512: row+16 keeps swizzle bit
    unsigned boff = SWZOFF(nw + (lane & 15), lane >> 4);

    float acc1[4][2][4] = {}, acc3[4][2][4] = {};

    load_stage(0);
    load_stage(1);

    const int NKT = DIM / 16;   // 64
    for (int kt = 0; kt < NKT; kt++) {
        if (kt < NKT-1) CP_WAIT1(); else CP_WAIT0();
        __syncthreads();
        if (kt + 2 < NKT) load_stage(kt + 2);

        unsigned st = sbase + (kt % 3)*ST1;
        unsigned ah[4][4], al[4][4];
        #pragma unroll
        for (int mt = 0; mt < 4; mt++) {
            ldsm4(ah[mt], st + aoff + mt*512);
            ldsm4(al[mt], st + 4096 + aoff + mt*512);
        }
        unsigned t1h[4], t1l[4], t3h[4], t3l[4];
        ldsm4(t1h, st + 8192  + boff);
        ldsm4(t1l, st + 10240 + boff);
        ldsm4(t3h, st + 12288 + boff);
        ldsm4(t3l, st + 14336 + boff);
        #pragma unroll
        for (int mt = 0; mt < 4; mt++)
            #pragma unroll
            for (int nt = 0; nt < 2; nt++) {
                mma16816(acc1[mt][nt], ah[mt], t1h[nt], t1h[nt+2]);
                mma16816(acc1[mt][nt], ah[mt], t1l[nt], t1l[nt+2]);
                mma16816(acc1[mt][nt], al[mt], t1h[nt], t1h[nt+2]);
                mma16816(acc3[mt][nt], ah[mt], t3h[nt], t3h[nt+2]);
                mma16816(acc3[mt][nt], ah[mt], t3l[nt], t3l[nt+2]);
                mma16816(acc3[mt][nt], al[mt], t3h[nt], t3h[nt+2]);
            }
        __syncthreads();
    }

    // epilogue: SwiGLU -> Hh/Hl
    #pragma unroll
    for (int mt = 0; mt < 4; mt++) {
        int r = row0 + m0 + mt*16 + (lane >> 2);
        #pragma unroll
        for (int nt = 0; nt < 2; nt++) {
            int col = ncol + nw + nt*8 + (lane & 3)*2;
            #pragma unroll
            for (int half = 0; half < 2; half++) {
                int rr = r + half*8;
                if (rr >= row_end) continue;
                float a0 = acc1[mt][nt][2*half], a1 = acc1[mt][nt][2*half+1];
                float c0 = acc3[mt][nt][2*half], c1 = acc3[mt][nt][2*half+1];
                float h0 = a0 / (1.f + __expf(-a0)) * c0;
                float h1 = a1 / (1.f + __expf(-a1)) * c1;
                __nv_bfloat16 b0 = __float2bfloat16(h0), b1 = __float2bfloat16(h1);
                float l0 = h0 - __bfloat162float(b0), l1 = h1 - __bfloat162float(b1);
                unsigned hv = (unsigned)__bfloat16_as_ushort(b0) | ((unsigned)__bfloat16_as_ushort(b1) << 16);
                unsigned lv = (unsigned)__bfloat16_as_ushort(__float2bfloat16(l0))
                            | ((unsigned)__bfloat16_as_ushort(__float2bfloat16(l1)) << 16);
                *(unsigned*)(g_Hh + (size_t)rr*FDIM + col) = hv;
                *(unsigned*)(g_Hl + (size_t)rr*FDIM + col) = lv;
            }
        }
    }
}

// ---------------- GEMM2: Og = (H @ W2) * route_weight ----------------
__global__ __launch_bounds__(256, 2) void k_gemm2() {
    int e = g_tile_e[blockIdx.y];
    if (e < 0) return;
    int row0 = g_tile_r[blockIdx.y];
    int row_end = g_offs[e + 1];
    int ncol = blockIdx.x * 64;

    __shared__ __align__(128) char sm[3*ST2];
    unsigned sbase = smem_u32(sm);
    int tid = threadIdx.x, lane = tid & 31, wid = tid >> 5;

    int rowA = tid >> 1, vecA = tid & 1;
    int ar = row0 + rowA; if (ar > TOTAL-1) ar = TOTAL-1;
    const __nv_bfloat16* gAh = g_Hh + (size_t)ar*FDIM + vecA*8;
    const __nv_bfloat16* gAl = g_Hl + (size_t)ar*FDIM + vecA*8;
    unsigned sA = SWZOFF(rowA, vecA);

    size_t eoff = (size_t)e*FDIM*DIM + (size_t)ncol*FDIM;
    int q = tid >> 7, iB = tid & 127, rB = iB >> 1, vB = iB & 1;
    const __nv_bfloat16* gB = (q == 0 ? g_W2h : g_W2l) + eoff + (size_t)rB*FDIM + vB*8;
    unsigned sB = 8192 + q*2048 + SWZOFF(rB, vB);

    auto load_stage = [&](int kt) {
        unsigned st = sbase + (kt % 3)*ST2;
        int ko = kt * 16;
        cp16(st + sA,        gAh + ko);
        cp16(st + 4096 + sA, gAl + ko);
        cp16(st + sB,        gB + ko);
        CP_COMMIT();
    };

    int m0 = (wid & 1) * 64, nw = (wid >> 1) * 16;
    unsigned aoff = SWZOFF(m0 + (lane & 15), lane >> 4);
    unsigned boff = SWZOFF(nw + (lane & 15), lane >> 4);

    float acc[4][2][4] = {};

    load_stage(0);
    load_stage(1);

    const int NKT = FDIM / 16;  // 256
    for (int kt = 0; kt < NKT; kt++) {
        if (kt < NKT-1) CP_WAIT1(); else CP_WAIT0();
        __syncthreads();
        if (kt + 2 < NKT) load_stage(kt + 2);

        unsigned st = sbase + (kt % 3)*ST2;
        unsigned ah[4][4], al[4][4];
        #pragma unroll
        for (int mt = 0; mt < 4; mt++) {
            ldsm4(ah[mt], st + aoff + mt*512);
            ldsm4(al[mt], st + 4096 + aoff + mt*512);
        }
        unsigned tbh[4], tbl[4];
        ldsm4(tbh, st + 8192  + boff);
        ldsm4(tbl, st + 10240 + boff);
        #pragma unroll
        for (int mt = 0; mt < 4; mt++)
            #pragma unroll
            for (int nt = 0; nt < 2; nt++) {
                mma16816(acc[mt][nt], ah[mt], tbh[nt], tbh[nt+2]);
                mma16816(acc[mt][nt], ah[mt], tbl[nt], tbl[nt+2]);
                mma16816(acc[mt][nt], al[mt], tbh[nt], tbh[nt+2]);
            }
        __syncthreads();
    }

    #pragma unroll
    for (int mt = 0; mt < 4; mt++) {
        int r = row0 + m0 + mt*16 + (lane >> 2);
        #pragma unroll
        for (int nt = 0; nt < 2; nt++) {
            int col = ncol + nw + nt*8 + (lane & 3)*2;
            #pragma unroll
            for (int half = 0; half < 2; half++) {
                int rr = r + half*8;
                if (rr >= row_end) continue;
                float wg = g_wgt[rr];
                *(float2*)(g_Og + (size_t)rr*DIM + col) =
                    make_float2(acc[mt][nt][2*half]*wg, acc[mt][nt][2*half+1]*wg);
            }
        }
    }
}

// ---------------- combine ----------------
__global__ void k_combine(float* __restrict__ out) {
    int t = blockIdx.x;
    int s0 = g_slot[2*t], s1 = g_slot[2*t+1];
    float4 a = ((const float4*)(g_Og + (size_t)s0 * DIM))[threadIdx.x];
    float4 b = ((const float4*)(g_Og + (size_t)s1 * DIM))[threadIdx.x];
    ((float4*)(out + (size_t)t * DIM))[threadIdx.x] =
        make_float4(a.x + b.x, a.y + b.y, a.z + b.z, a.w + b.w);
}

// ---------------- launch ----------------
extern "C" void kernel_launch(void* const* d_in, const int* in_sizes, int n_in,
                              void* d_out, int out_size) {
    const float* x  = (const float*)d_in[0];
    const float* gw = (const float*)d_in[1];
    const float* w1 = (const float*)d_in[2];
    const float* w2 = (const float*)d_in[3];
    const float* w3 = (const float*)d_in[4];
    float* out = (float*)d_out;

    k_zero<<<1, 32>>>();
    k_gate<<<T_TOK / 8, 256>>>(x, gw);
    k_scan<<<1, 32>>>();
    k_scatter<<<TOTAL / 256, 256>>>();
    k_gather<<<TOTAL, 256>>>(x);
    k_wsplit<<<dim3(FDIM/32, DIM/32, NEXP), dim3(32, 8)>>>(w1, 0, DIM, FDIM);
    k_wsplit<<<dim3(FDIM/32, DIM/32, NEXP), dim3(32, 8)>>>(w3, 1, DIM, FDIM);
    k_wsplit<<<dim3(DIM/32, FDIM/32, NEXP), dim3(32, 8)>>>(w2, 2, FDIM, DIM);
    k_gemm1<<<dim3(FDIM/64, MAX_TILES), 256>>>();    // 64 x 136
    k_gemm2<<<dim3(DIM/64,  MAX_TILES), 256>>>();    // 16 x 136
    k_combine<<<T_TOK, 256>>>(out);
}

// round 15
// speedup vs baseline: 2.0897x; 1.0207x over previous
#include <cuda_runtime.h>
#include <cuda_bf16.h>
#include <math.h>

// ---------------- problem constants ----------------
#define T_TOK 8192
#define DIM   1024
#define FDIM  4096
#define NEXP  8
#define TOTAL (T_TOK*2)               // 16384 routed rows (exact invariant)
#define BM 128
#define MAX_TILES (TOTAL/BM + NEXP)   // 136

// BK=32 stages, 64B-pitch swizzled rows, 3-stage cp.async (dynamic smem)
// GEMM1 stage: Ah,Al 128x64B + B1h,B1l,B3h,B3l 64x64B = 32768
// GEMM2 stage: Ah,Al 128x64B + Bh,Bl 64x64B = 24576
#define ST1 32768
#define ST2 24576

// ---------------- device scratch (~768 MB total) ----------------
__device__ __align__(16) __nv_bfloat16 g_Xh[(size_t)TOTAL*DIM];
__device__ __align__(16) __nv_bfloat16 g_Xl[(size_t)TOTAL*DIM];
__device__ __align__(16) __nv_bfloat16 g_Hh[(size_t)TOTAL*FDIM];
__device__ __align__(16) __nv_bfloat16 g_Hl[(size_t)TOTAL*FDIM];
__device__ __align__(16) __nv_bfloat16 g_W1h[(size_t)NEXP*DIM*FDIM];
__device__ __align__(16) __nv_bfloat16 g_W1l[(size_t)NEXP*DIM*FDIM];
__device__ __align__(16) __nv_bfloat16 g_W3h[(size_t)NEXP*DIM*FDIM];
__device__ __align__(16) __nv_bfloat16 g_W3l[(size_t)NEXP*DIM*FDIM];
__device__ __align__(16) __nv_bfloat16 g_W2h[(size_t)NEXP*FDIM*DIM];
__device__ __align__(16) __nv_bfloat16 g_W2l[(size_t)NEXP*FDIM*DIM];
__device__ __align__(16) float g_Og[(size_t)TOTAL*DIM];
__device__ int   g_tok[TOTAL];
__device__ float g_wgt[TOTAL];
__device__ int   g_slot[TOTAL];
__device__ int   g_topk_idx[TOTAL];
__device__ float g_topk_w[TOTAL];
__device__ int   g_counts[NEXP];
__device__ int   g_offs[NEXP+1];
__device__ int   g_cursor[NEXP];
__device__ int   g_tile_e[MAX_TILES];
__device__ int   g_tile_r[MAX_TILES];

// ---------------- PTX helpers (sm_80-class only) ----------------
__device__ __forceinline__ unsigned smem_u32(const void* p) {
    unsigned a;
    asm("{ .reg .u64 t; cvta.to.shared.u64 t, %1; cvt.u32.u64 %0, t; }" : "=r"(a) : "l"(p));
    return a;
}
__device__ __forceinline__ void cp16(unsigned dst, const void* src) {
    asm volatile("cp.async.cg.shared.global [%0], [%1], 16;" :: "r"(dst), "l"(src) : "memory");
}
#define CP_COMMIT() asm volatile("cp.async.commit_group;" ::: "memory")
#define CP_WAIT1()  asm volatile("cp.async.wait_group 1;" ::: "memory")
#define CP_WAIT0()  asm volatile("cp.async.wait_group 0;" ::: "memory")

// 64B-pitch row swizzle: row r, 16B-vec v(0..3): quad(r,v)=(4r+(v^((r>>1)&3)))%8
// hits all 8 bank-quads in every ldmatrix 8-row phase (verified r=0..7 x v=0..3).
#define SW64(r, v) ((unsigned)(r)*64u + ((((unsigned)(v)) ^ (((unsigned)(r)>>1)&3u))&3u)*16u)

__device__ __forceinline__ void ldsm4(unsigned r[4], unsigned addr) {
    asm volatile("ldmatrix.sync.aligned.m8n8.x4.shared.b16 {%0,%1,%2,%3}, [%4];"
                 : "=r"(r[0]), "=r"(r[1]), "=r"(r[2]), "=r"(r[3]) : "r"(addr));
}
__device__ __forceinline__ void mma16816(float d[4], const unsigned a[4], unsigned b0, unsigned b1) {
    asm volatile("mma.sync.aligned.m16n8k16.row.col.f32.bf16.bf16.f32 "
                 "{%0,%1,%2,%3}, {%4,%5,%6,%7}, {%8,%9}, {%0,%1,%2,%3};"
                 : "+f"(d[0]), "+f"(d[1]), "+f"(d[2]), "+f"(d[3])
                 : "r"(a[0]), "r"(a[1]), "r"(a[2]), "r"(a[3]), "r"(b0), "r"(b1));
}

// ---------------- routing kernels (proven) ----------------
__global__ void k_zero() { if (threadIdx.x < NEXP) g_counts[threadIdx.x] = 0; }

__global__ void k_gate(const float* __restrict__ x, const float* __restrict__ gw) {
    int warp = threadIdx.x >> 5, lane = threadIdx.x & 31;
    int t = blockIdx.x * 8 + warp;
    const float* xr = x + (size_t)t * DIM;
    float acc[NEXP];
    #pragma unroll
    for (int e = 0; e < NEXP; e++) acc[e] = 0.f;
    #pragma unroll 4
    for (int it = 0; it < DIM/32; it++) {
        int d = it*32 + lane;
        float xv = xr[d];
        const float4* g4 = (const float4*)(gw + (size_t)d * NEXP);
        float4 ga = g4[0], gb = g4[1];
        acc[0] += xv*ga.x; acc[1] += xv*ga.y; acc[2] += xv*ga.z; acc[3] += xv*ga.w;
        acc[4] += xv*gb.x; acc[5] += xv*gb.y; acc[6] += xv*gb.z; acc[7] += xv*gb.w;
    }
    #pragma unroll
    for (int e = 0; e < NEXP; e++)
        #pragma unroll
        for (int off = 16; off > 0; off >>= 1)
            acc[e] += __shfl_xor_sync(0xffffffffu, acc[e], off);
    if (lane == 0) {
        float v0 = -INFINITY, v1 = -INFINITY; int i0 = 0, i1 = 0;
        #pragma unroll
        for (int e = 0; e < NEXP; e++) {
            float s = acc[e];
            if (s > v0)      { v1 = v0; i1 = i0; v0 = s; i0 = e; }
            else if (s > v1) { v1 = s;  i1 = e; }
        }
        float e1 = expf(v1 - v0);
        float inv = 1.f / (1.f + e1);
        g_topk_idx[2*t]   = i0; g_topk_w[2*t]   = inv;
        g_topk_idx[2*t+1] = i1; g_topk_w[2*t+1] = e1 * inv;
        atomicAdd(&g_counts[i0], 1);
        atomicAdd(&g_counts[i1], 1);
    }
}

__global__ void k_scan() {
    if (threadIdx.x != 0) return;
    int off = 0;
    for (int e = 0; e < NEXP; e++) { g_offs[e] = off; g_cursor[e] = off; off += g_counts[e]; }
    g_offs[NEXP] = off;
    int tc = 0;
    for (int e = 0; e < NEXP; e++)
        for (int r = 0; r < g_counts[e]; r += BM) { g_tile_e[tc] = e; g_tile_r[tc] = g_offs[e] + r; tc++; }
    for (; tc < MAX_TILES; tc++) g_tile_e[tc] = -1;
}

__global__ void k_scatter() {
    int i = blockIdx.x * blockDim.x + threadIdx.x;
    if (i >= TOTAL) return;
    int e = g_topk_idx[i];
    int p = atomicAdd(&g_cursor[e], 1);
    g_tok[p] = i >> 1; g_wgt[p] = g_topk_w[i]; g_slot[i] = p;
}

__global__ void k_gather(const float* __restrict__ x) {
    int p = blockIdx.x, t = g_tok[p];
    float4 v = ((const float4*)(x + (size_t)t * DIM))[threadIdx.x];
    float f[4] = {v.x, v.y, v.z, v.w};
    unsigned hs[4], ls[4];
    #pragma unroll
    for (int i = 0; i < 4; i++) {
        __nv_bfloat16 h = __float2bfloat16(f[i]);
        float lo = f[i] - __bfloat162float(h);
        hs[i] = __bfloat16_as_ushort(h);
        ls[i] = __bfloat16_as_ushort(__float2bfloat16(lo));
    }
    ((uint2*)(g_Xh + (size_t)p * DIM))[threadIdx.x] = make_uint2(hs[0]|(hs[1]<<16), hs[2]|(hs[3]<<16));
    ((uint2*)(g_Xl + (size_t)p * DIM))[threadIdx.x] = make_uint2(ls[0]|(ls[1]<<16), ls[2]|(ls[3]<<16));
}

// transpose + split weights; outputs selected INSIDE device code (ATS-bug fix, R11-proven)
__global__ void k_wsplit(const float* __restrict__ W, int sel, int R, int C) {
    __nv_bfloat16 *oh, *ol;
    if      (sel == 0) { oh = g_W1h; ol = g_W1l; }
    else if (sel == 1) { oh = g_W3h; ol = g_W3l; }
    else               { oh = g_W2h; ol = g_W2l; }
    __shared__ float tb[32][33];
    const float* Wb = W + (size_t)blockIdx.z * R * C;
    size_t ob = (size_t)blockIdx.z * R * C;
    int tx = threadIdx.x, ty = threadIdx.y;
    #pragma unroll
    for (int i = 0; i < 4; i++) {
        int r = blockIdx.y*32 + ty + i*8;
        tb[ty + i*8][tx] = Wb[(size_t)r * C + blockIdx.x*32 + tx];
    }
    __syncthreads();
    int rr = blockIdx.y*32 + tx;
    #pragma unroll
    for (int i = 0; i < 4; i++) {
        int cc = blockIdx.x*32 + ty + i*8;
        float v = tb[tx][ty + i*8];
        __nv_bfloat16 h = __float2bfloat16(v);
        float lo = v - __bfloat162float(h);
        size_t o = ob + (size_t)cc * R + rr;
        oh[o] = h; ol[o] = __float2bfloat16(lo);
    }
}

// ---------------- GEMM1 (fused SwiGLU): H = silu(X@W1)*(X@W3), split-3 bf16 ----------------
// CTA 128(M) x 64(N), BK=32 (2 x k16), 256 thr, 8 warps (2M x 4N), warp 64x16.
__global__ __launch_bounds__(256, 2) void k_gemm1() {
    int e = g_tile_e[blockIdx.y];
    if (e < 0) return;
    int row0 = g_tile_r[blockIdx.y];
    int row_end = g_offs[e + 1];
    int ncol = blockIdx.x * 64;

    extern __shared__ __align__(128) char sm[];
    unsigned sbase = smem_u32(sm);
    int tid = threadIdx.x, lane = tid & 31, wid = tid >> 5;

    // ---- cp.async mapping
    // A: row=tid>>1, vec-pair=(tid&1)*2 -> 2 cp16 per A tile
    int rowA = tid >> 1, vA = (tid & 1) * 2;
    int ar = row0 + rowA; if (ar > TOTAL-1) ar = TOTAL-1;
    const __nv_bfloat16* gAh = g_Xh + (size_t)ar*DIM + vA*8;
    const __nv_bfloat16* gAl = g_Xl + (size_t)ar*DIM + vA*8;
    unsigned sA0 = SW64(rowA, vA), sA1 = SW64(rowA, vA + 1);
    // B: row=tid>>2, vec=tid&3 -> 1 cp16 per each of 4 B tiles
    int rB = tid >> 2, vB = tid & 3;
    size_t eoff = (size_t)e*DIM*FDIM + (size_t)ncol*DIM;
    const __nv_bfloat16* gB1h = g_W1h + eoff + (size_t)rB*DIM + vB*8;
    const __nv_bfloat16* gB1l = g_W1l + eoff + (size_t)rB*DIM + vB*8;
    const __nv_bfloat16* gB3h = g_W3h + eoff + (size_t)rB*DIM + vB*8;
    const __nv_bfloat16* gB3l = g_W3l + eoff + (size_t)rB*DIM + vB*8;
    unsigned sB = SW64(rB, vB);

    auto load_stage = [&](int kt) {
        unsigned st = sbase + (kt % 3)*ST1;
        int ko = kt * 32;
        cp16(st + sA0,         gAh + ko);
        cp16(st + sA1,         gAh + ko + 8);
        cp16(st + 8192 + sA0,  gAl + ko);
        cp16(st + 8192 + sA1,  gAl + ko + 8);
        cp16(st + 16384 + sB,  gB1h + ko);
        cp16(st + 20480 + sB,  gB1l + ko);
        cp16(st + 24576 + sB,  gB3h + ko);
        cp16(st + 28672 + sB,  gB3l + ko);
        CP_COMMIT();
    };

    // ---- compute mapping (per k16 sub-step s: vec = 2s + (lane>>4))
    int m0 = (wid & 1) * 64, nw = (wid >> 1) * 16;
    unsigned aoff[2], boff[2];
    #pragma unroll
    for (int s = 0; s < 2; s++) {
        aoff[s] = SW64(m0 + (lane & 15), 2*s + (lane >> 4));
        boff[s] = SW64(nw + (lane & 15), 2*s + (lane >> 4));
    }

    float acc1[4][2][4] = {}, acc3[4][2][4] = {};

    load_stage(0);
    load_stage(1);

    const int NKT = DIM / 32;   // 32
    for (int kt = 0; kt < NKT; kt++) {
        if (kt < NKT-1) CP_WAIT1(); else CP_WAIT0();
        __syncthreads();
        if (kt + 2 < NKT) load_stage(kt + 2);

        unsigned st = sbase + (kt % 3)*ST1;
        #pragma unroll
        for (int s = 0; s < 2; s++) {
            unsigned t1h[4], t1l[4], t3h[4], t3l[4];
            ldsm4(t1h, st + 16384 + boff[s]);
            ldsm4(t1l, st + 20480 + boff[s]);
            ldsm4(t3h, st + 24576 + boff[s]);
            ldsm4(t3l, st + 28672 + boff[s]);
            #pragma unroll
            for (int mt = 0; mt < 4; mt++) {
                unsigned ah[4], al[4];
                ldsm4(ah, st + aoff[s] + mt*1024);
                ldsm4(al, st + 8192 + aoff[s] + mt*1024);
                #pragma unroll
                for (int nt = 0; nt < 2; nt++) {
                    mma16816(acc1[mt][nt], ah, t1h[nt], t1h[nt+2]);
                    mma16816(acc1[mt][nt], ah, t1l[nt], t1l[nt+2]);
                    mma16816(acc1[mt][nt], al, t1h[nt], t1h[nt+2]);
                    mma16816(acc3[mt][nt], ah, t3h[nt], t3h[nt+2]);
                    mma16816(acc3[mt][nt], ah, t3l[nt], t3l[nt+2]);
                    mma16816(acc3[mt][nt], al, t3h[nt], t3h[nt+2]);
                }
            }
        }
        __syncthreads();
    }

    // epilogue: SwiGLU -> Hh/Hl
    #pragma unroll
    for (int mt = 0; mt < 4; mt++) {
        int r = row0 + m0 + mt*16 + (lane >> 2);
        #pragma unroll
        for (int nt = 0; nt < 2; nt++) {
            int col = ncol + nw + nt*8 + (lane & 3)*2;
            #pragma unroll
            for (int half = 0; half < 2; half++) {
                int rr = r + half*8;
                if (rr >= row_end) continue;
                float a0 = acc1[mt][nt][2*half], a1 = acc1[mt][nt][2*half+1];
                float c0 = acc3[mt][nt][2*half], c1 = acc3[mt][nt][2*half+1];
                float h0 = a0 / (1.f + __expf(-a0)) * c0;
                float h1 = a1 / (1.f + __expf(-a1)) * c1;
                __nv_bfloat16 b0 = __float2bfloat16(h0), b1 = __float2bfloat16(h1);
                float l0 = h0 - __bfloat162float(b0), l1 = h1 - __bfloat162float(b1);
                unsigned hv = (unsigned)__bfloat16_as_ushort(b0) | ((unsigned)__bfloat16_as_ushort(b1) << 16);
                unsigned lv = (unsigned)__bfloat16_as_ushort(__float2bfloat16(l0))
                            | ((unsigned)__bfloat16_as_ushort(__float2bfloat16(l1)) << 16);
                *(unsigned*)(g_Hh + (size_t)rr*FDIM + col) = hv;
                *(unsigned*)(g_Hl + (size_t)rr*FDIM + col) = lv;
            }
        }
    }
}

// ---------------- GEMM2: Og = (H @ W2) * route_weight ----------------
__global__ __launch_bounds__(256, 2) void k_gemm2() {
    int e = g_tile_e[blockIdx.y];
    if (e < 0) return;
    int row0 = g_tile_r[blockIdx.y];
    int row_end = g_offs[e + 1];
    int ncol = blockIdx.x * 64;

    extern __shared__ __align__(128) char sm[];
    unsigned sbase = smem_u32(sm);
    int tid = threadIdx.x, lane = tid & 31, wid = tid >> 5;

    int rowA = tid >> 1, vA = (tid & 1) * 2;
    int ar = row0 + rowA; if (ar > TOTAL-1) ar = TOTAL-1;
    const __nv_bfloat16* gAh = g_Hh + (size_t)ar*FDIM + vA*8;
    const __nv_bfloat16* gAl = g_Hl + (size_t)ar*FDIM + vA*8;
    unsigned sA0 = SW64(rowA, vA), sA1 = SW64(rowA, vA + 1);

    int rB = tid >> 2, vB = tid & 3;
    size_t eoff = (size_t)e*FDIM*DIM + (size_t)ncol*FDIM;
    const __nv_bfloat16* gBh = g_W2h + eoff + (size_t)rB*FDIM + vB*8;
    const __nv_bfloat16* gBl = g_W2l + eoff + (size_t)rB*FDIM + vB*8;
    unsigned sB = SW64(rB, vB);

    auto load_stage = [&](int kt) {
        unsigned st = sbase + (kt % 3)*ST2;
        int ko = kt * 32;
        cp16(st + sA0,        gAh + ko);
        cp16(st + sA1,        gAh + ko + 8);
        cp16(st + 8192 + sA0, gAl + ko);
        cp16(st + 8192 + sA1, gAl + ko + 8);
        cp16(st + 16384 + sB, gBh + ko);
        cp16(st + 20480 + sB, gBl + ko);
        CP_COMMIT();
    };

    int m0 = (wid & 1) * 64, nw = (wid >> 1) * 16;
    unsigned aoff[2], boff[2];
    #pragma unroll
    for (int s = 0; s < 2; s++) {
        aoff[s] = SW64(m0 + (lane & 15), 2*s + (lane >> 4));
        boff[s] = SW64(nw + (lane & 15), 2*s + (lane >> 4));
    }

    float acc[4][2][4] = {};

    load_stage(0);
    load_stage(1);

    const int NKT = FDIM / 32;  // 128
    for (int kt = 0; kt < NKT; kt++) {
        if (kt < NKT-1) CP_WAIT1(); else CP_WAIT0();
        __syncthreads();
        if (kt + 2 < NKT) load_stage(kt + 2);

        unsigned st = sbase + (kt % 3)*ST2;
        #pragma unroll
        for (int s = 0; s < 2; s++) {
            unsigned tbh[4], tbl[4];
            ldsm4(tbh, st + 16384 + boff[s]);
            ldsm4(tbl, st + 20480 + boff[s]);
            #pragma unroll
            for (int mt = 0; mt < 4; mt++) {
                unsigned ah[4], al[4];
                ldsm4(ah, st + aoff[s] + mt*1024);
                ldsm4(al, st + 8192 + aoff[s] + mt*1024);
                #pragma unroll
                for (int nt = 0; nt < 2; nt++) {
                    mma16816(acc[mt][nt], ah, tbh[nt], tbh[nt+2]);
                    mma16816(acc[mt][nt], ah, tbl[nt], tbl[nt+2]);
                    mma16816(acc[mt][nt], al, tbh[nt], tbh[nt+2]);
                }
            }
        }
        __syncthreads();
    }

    #pragma unroll
    for (int mt = 0; mt < 4; mt++) {
        int r = row0 + m0 + mt*16 + (lane >> 2);
        #pragma unroll
        for (int nt = 0; nt < 2; nt++) {
            int col = ncol + nw + nt*8 + (lane & 3)*2;
            #pragma unroll
            for (int half = 0; half < 2; half++) {
                int rr = r + half*8;
                if (rr >= row_end) continue;
                float wg = g_wgt[rr];
                *(float2*)(g_Og + (size_t)rr*DIM + col) =
                    make_float2(acc[mt][nt][2*half]*wg, acc[mt][nt][2*half+1]*wg);
            }
        }
    }
}

// ---------------- combine ----------------
__global__ void k_combine(float* __restrict__ out) {
    int t = blockIdx.x;
    int s0 = g_slot[2*t], s1 = g_slot[2*t+1];
    float4 a = ((const float4*)(g_Og + (size_t)s0 * DIM))[threadIdx.x];
    float4 b = ((const float4*)(g_Og + (size_t)s1 * DIM))[threadIdx.x];
    ((float4*)(out + (size_t)t * DIM))[threadIdx.x] =
        make_float4(a.x + b.x, a.y + b.y, a.z + b.z, a.w + b.w);
}

// ---------------- launch ----------------
extern "C" void kernel_launch(void* const* d_in, const int* in_sizes, int n_in,
                              void* d_out, int out_size) {
    const float* x  = (const float*)d_in[0];
    const float* gw = (const float*)d_in[1];
    const float* w1 = (const float*)d_in[2];
    const float* w2 = (const float*)d_in[3];
    const float* w3 = (const float*)d_in[4];
    float* out = (float*)d_out;

    cudaFuncSetAttribute(k_gemm1, cudaFuncAttributeMaxDynamicSharedMemorySize, 3*ST1);
    cudaFuncSetAttribute(k_gemm2, cudaFuncAttributeMaxDynamicSharedMemorySize, 3*ST2);

    k_zero<<<1, 32>>>();
    k_gate<<<T_TOK / 8, 256>>>(x, gw);
    k_scan<<<1, 32>>>();
    k_scatter<<<TOTAL / 256, 256>>>();
    k_gather<<<TOTAL, 256>>>(x);
    k_wsplit<<<dim3(FDIM/32, DIM/32, NEXP), dim3(32, 8)>>>(w1, 0, DIM, FDIM);
    k_wsplit<<<dim3(FDIM/32, DIM/32, NEXP), dim3(32, 8)>>>(w3, 1, DIM, FDIM);
    k_wsplit<<<dim3(DIM/32, FDIM/32, NEXP), dim3(32, 8)>>>(w2, 2, FDIM, DIM);
    k_gemm1<<<dim3(FDIM/64, MAX_TILES), 256, 3*ST1>>>();   // 64 x 136
    k_gemm2<<<dim3(DIM/64,  MAX_TILES), 256, 3*ST2>>>();   // 16 x 136
    k_combine<<<T_TOK, 256>>>(out);
}

// round 16
// speedup vs baseline: 2.8128x; 1.3460x over previous
#include <cuda_runtime.h>
#include <cuda_fp16.h>
#include <math.h>

// ---------------- problem constants ----------------
#define T_TOK 8192
#define DIM   1024
#define FDIM  4096
#define NEXP  8
#define TOTAL (T_TOK*2)               // 16384 routed rows (exact invariant)
#define BM 128
#define MAX_TILES (TOTAL/BM + NEXP)   // 136

// fp16 split-2 (A hi/lo, B hi only), BK=32, 64B-pitch swizzled rows, 3-stage cp.async
// GEMM1 stage: Xh,Xl 128x64B + W1h,W3h 64x64B = 24576
// GEMM2 stage: Hh,Hl 128x64B + W2h 64x64B     = 20480
#define ST1 24576
#define ST2 20480

// ---------------- device scratch ----------------
__device__ __align__(16) __half g_Xh[(size_t)TOTAL*DIM];
__device__ __align__(16) __half g_Xl[(size_t)TOTAL*DIM];
__device__ __align__(16) __half g_Hh[(size_t)TOTAL*FDIM];
__device__ __align__(16) __half g_Hl[(size_t)TOTAL*FDIM];
__device__ __align__(16) __half g_W1h[(size_t)NEXP*DIM*FDIM];
__device__ __align__(16) __half g_W3h[(size_t)NEXP*DIM*FDIM];
__device__ __align__(16) __half g_W2h[(size_t)NEXP*FDIM*DIM];
__device__ __align__(16) float g_Og[(size_t)TOTAL*DIM];
__device__ int   g_tok[TOTAL];
__device__ float g_wgt[TOTAL];
__device__ int   g_slot[TOTAL];
__device__ int   g_topk_idx[TOTAL];
__device__ float g_topk_w[TOTAL];
__device__ int   g_counts[NEXP];
__device__ int   g_offs[NEXP+1];
__device__ int   g_cursor[NEXP];
__device__ int   g_tile_e[MAX_TILES];
__device__ int   g_tile_r[MAX_TILES];

// ---------------- PTX helpers (sm_80-class only) ----------------
__device__ __forceinline__ unsigned smem_u32(const void* p) {
    unsigned a;
    asm("{ .reg .u64 t; cvta.to.shared.u64 t, %1; cvt.u32.u64 %0, t; }" : "=r"(a) : "l"(p));
    return a;
}
__device__ __forceinline__ void cp16(unsigned dst, const void* src) {
    asm volatile("cp.async.cg.shared.global [%0], [%1], 16;" :: "r"(dst), "l"(src) : "memory");
}
#define CP_COMMIT() asm volatile("cp.async.commit_group;" ::: "memory")
#define CP_WAIT1()  asm volatile("cp.async.wait_group 1;" ::: "memory")
#define CP_WAIT0()  asm volatile("cp.async.wait_group 0;" ::: "memory")

// 64B-pitch row swizzle: row r, 16B-vec v(0..3): quad(r,v)=(4r+(v^((r>>1)&3)))%8
// hits all 8 bank-quads in every ldmatrix 8-row phase (verified r=0..7 x v=0..3).
#define SW64(r, v) ((unsigned)(r)*64u + ((((unsigned)(v)) ^ (((unsigned)(r)>>1)&3u))&3u)*16u)

__device__ __forceinline__ void ldsm4(unsigned r[4], unsigned addr) {
    asm volatile("ldmatrix.sync.aligned.m8n8.x4.shared.b16 {%0,%1,%2,%3}, [%4];"
                 : "=r"(r[0]), "=r"(r[1]), "=r"(r[2]), "=r"(r[3]) : "r"(addr));
}
__device__ __forceinline__ void mma16816(float d[4], const unsigned a[4], unsigned b0, unsigned b1) {
    asm volatile("mma.sync.aligned.m16n8k16.row.col.f32.f16.f16.f32 "
                 "{%0,%1,%2,%3}, {%4,%5,%6,%7}, {%8,%9}, {%0,%1,%2,%3};"
                 : "+f"(d[0]), "+f"(d[1]), "+f"(d[2]), "+f"(d[3])
                 : "r"(a[0]), "r"(a[1]), "r"(a[2]), "r"(a[3]), "r"(b0), "r"(b1));
}

// ---------------- routing kernels (proven) ----------------
__global__ void k_zero() { if (threadIdx.x < NEXP) g_counts[threadIdx.x] = 0; }

__global__ void k_gate(const float* __restrict__ x, const float* __restrict__ gw) {
    int warp = threadIdx.x >> 5, lane = threadIdx.x & 31;
    int t = blockIdx.x * 8 + warp;
    const float* xr = x + (size_t)t * DIM;
    float acc[NEXP];
    #pragma unroll
    for (int e = 0; e < NEXP; e++) acc[e] = 0.f;
    #pragma unroll 4
    for (int it = 0; it < DIM/32; it++) {
        int d = it*32 + lane;
        float xv = xr[d];
        const float4* g4 = (const float4*)(gw + (size_t)d * NEXP);
        float4 ga = g4[0], gb = g4[1];
        acc[0] += xv*ga.x; acc[1] += xv*ga.y; acc[2] += xv*ga.z; acc[3] += xv*ga.w;
        acc[4] += xv*gb.x; acc[5] += xv*gb.y; acc[6] += xv*gb.z; acc[7] += xv*gb.w;
    }
    #pragma unroll
    for (int e = 0; e < NEXP; e++)
        #pragma unroll
        for (int off = 16; off > 0; off >>= 1)
            acc[e] += __shfl_xor_sync(0xffffffffu, acc[e], off);
    if (lane == 0) {
        float v0 = -INFINITY, v1 = -INFINITY; int i0 = 0, i1 = 0;
        #pragma unroll
        for (int e = 0; e < NEXP; e++) {
            float s = acc[e];
            if (s > v0)      { v1 = v0; i1 = i0; v0 = s; i0 = e; }
            else if (s > v1) { v1 = s;  i1 = e; }
        }
        float e1 = expf(v1 - v0);
        float inv = 1.f / (1.f + e1);
        g_topk_idx[2*t]   = i0; g_topk_w[2*t]   = inv;
        g_topk_idx[2*t+1] = i1; g_topk_w[2*t+1] = e1 * inv;
        atomicAdd(&g_counts[i0], 1);
        atomicAdd(&g_counts[i1], 1);
    }
}

__global__ void k_scan() {
    if (threadIdx.x != 0) return;
    int off = 0;
    for (int e = 0; e < NEXP; e++) { g_offs[e] = off; g_cursor[e] = off; off += g_counts[e]; }
    g_offs[NEXP] = off;
    int tc = 0;
    for (int e = 0; e < NEXP; e++)
        for (int r = 0; r < g_counts[e]; r += BM) { g_tile_e[tc] = e; g_tile_r[tc] = g_offs[e] + r; tc++; }
    for (; tc < MAX_TILES; tc++) g_tile_e[tc] = -1;
}

__global__ void k_scatter() {
    int i = blockIdx.x * blockDim.x + threadIdx.x;
    if (i >= TOTAL) return;
    int e = g_topk_idx[i];
    int p = atomicAdd(&g_cursor[e], 1);
    g_tok[p] = i >> 1; g_wgt[p] = g_topk_w[i]; g_slot[i] = p;
}

// gather + split to fp16 hi/lo
__global__ void k_gather(const float* __restrict__ x) {
    int p = blockIdx.x, t = g_tok[p];
    float4 v = ((const float4*)(x + (size_t)t * DIM))[threadIdx.x];
    float f[4] = {v.x, v.y, v.z, v.w};
    unsigned hs[4], ls[4];
    #pragma unroll
    for (int i = 0; i < 4; i++) {
        __half h = __float2half(f[i]);
        float lo = f[i] - __half2float(h);
        hs[i] = __half_as_ushort(h);
        ls[i] = __half_as_ushort(__float2half(lo));
    }
    ((uint2*)(g_Xh + (size_t)p * DIM))[threadIdx.x] = make_uint2(hs[0]|(hs[1]<<16), hs[2]|(hs[3]<<16));
    ((uint2*)(g_Xl + (size_t)p * DIM))[threadIdx.x] = make_uint2(ls[0]|(ls[1]<<16), ls[2]|(ls[3]<<16));
}

// transpose + convert weights: W[R][C] fp32 -> [C][R] fp16 (hi only).
// Outputs selected INSIDE device code (ATS-bug fix, R11-proven).
__global__ void k_wsplit(const float* __restrict__ W, int sel, int R, int C) {
    __half* oh;
    if      (sel == 0) oh = g_W1h;
    else if (sel == 1) oh = g_W3h;
    else               oh = g_W2h;
    __shared__ float tb[32][33];
    const float* Wb = W + (size_t)blockIdx.z * R * C;
    size_t ob = (size_t)blockIdx.z * R * C;
    int tx = threadIdx.x, ty = threadIdx.y;
    #pragma unroll
    for (int i = 0; i < 4; i++) {
        int r = blockIdx.y*32 + ty + i*8;
        tb[ty + i*8][tx] = Wb[(size_t)r * C + blockIdx.x*32 + tx];
    }
    __syncthreads();
    int rr = blockIdx.y*32 + tx;
    #pragma unroll
    for (int i = 0; i < 4; i++) {
        int cc = blockIdx.x*32 + ty + i*8;
        oh[ob + (size_t)cc * R + rr] = __float2half(tb[tx][ty + i*8]);
    }
}

// ---------------- GEMM1 (fused SwiGLU): H = silu(X@W1)*(X@W3), fp16 split-2 ----------------
// CTA 128(M) x 64(N), BK=32 (2 x k16), 256 thr, 8 warps (2M x 4N), warp 64x16.
__global__ __launch_bounds__(256, 2) void k_gemm1() {
    int e = g_tile_e[blockIdx.y];
    if (e < 0) return;
    int row0 = g_tile_r[blockIdx.y];
    int row_end = g_offs[e + 1];
    int ncol = blockIdx.x * 64;

    extern __shared__ __align__(128) char sm[];
    unsigned sbase = smem_u32(sm);
    int tid = threadIdx.x, lane = tid & 31, wid = tid >> 5;

    // ---- cp.async mapping
    int rowA = tid >> 1, vA = (tid & 1) * 2;
    int ar = row0 + rowA; if (ar > TOTAL-1) ar = TOTAL-1;
    const __half* gAh = g_Xh + (size_t)ar*DIM + vA*8;
    const __half* gAl = g_Xl + (size_t)ar*DIM + vA*8;
    unsigned sA0 = SW64(rowA, vA), sA1 = SW64(rowA, vA + 1);
    int rB = tid >> 2, vB = tid & 3;
    size_t eoff = (size_t)e*DIM*FDIM + (size_t)ncol*DIM;
    const __half* gB1 = g_W1h + eoff + (size_t)rB*DIM + vB*8;
    const __half* gB3 = g_W3h + eoff + (size_t)rB*DIM + vB*8;
    unsigned sB = SW64(rB, vB);

    auto load_stage = [&](int kt) {
        unsigned st = sbase + (kt % 3)*ST1;
        int ko = kt * 32;
        cp16(st + sA0,        gAh + ko);
        cp16(st + sA1,        gAh + ko + 8);
        cp16(st + 8192 + sA0, gAl + ko);
        cp16(st + 8192 + sA1, gAl + ko + 8);
        cp16(st + 16384 + sB, gB1 + ko);
        cp16(st + 20480 + sB, gB3 + ko);
        CP_COMMIT();
    };

    // ---- compute mapping (per k16 sub-step s: vec = 2s + (lane>>4))
    int m0 = (wid & 1) * 64, nw = (wid >> 1) * 16;
    unsigned aoff[2], boff[2];
    #pragma unroll
    for (int s = 0; s < 2; s++) {
        aoff[s] = SW64(m0 + (lane & 15), 2*s + (lane >> 4));
        boff[s] = SW64(nw + (lane & 15), 2*s + (lane >> 4));
    }

    float acc1[4][2][4] = {}, acc3[4][2][4] = {};

    load_stage(0);
    load_stage(1);

    const int NKT = DIM / 32;   // 32
    for (int kt = 0; kt < NKT; kt++) {
        if (kt < NKT-1) CP_WAIT1(); else CP_WAIT0();
        __syncthreads();
        if (kt + 2 < NKT) load_stage(kt + 2);

        unsigned st = sbase + (kt % 3)*ST1;
        #pragma unroll
        for (int s = 0; s < 2; s++) {
            unsigned t1h[4], t3h[4];
            ldsm4(t1h, st + 16384 + boff[s]);
            ldsm4(t3h, st + 20480 + boff[s]);
            #pragma unroll
            for (int mt = 0; mt < 4; mt++) {
                unsigned ah[4], al[4];
                ldsm4(ah, st + aoff[s] + mt*1024);
                ldsm4(al, st + 8192 + aoff[s] + mt*1024);
                #pragma unroll
                for (int nt = 0; nt < 2; nt++) {
                    mma16816(acc1[mt][nt], ah, t1h[nt], t1h[nt+2]);
                    mma16816(acc1[mt][nt], al, t1h[nt], t1h[nt+2]);
                    mma16816(acc3[mt][nt], ah, t3h[nt], t3h[nt+2]);
                    mma16816(acc3[mt][nt], al, t3h[nt], t3h[nt+2]);
                }
            }
        }
        __syncthreads();
    }

    // epilogue: SwiGLU -> Hh/Hl (fp16 hi/lo)
    #pragma unroll
    for (int mt = 0; mt < 4; mt++) {
        int r = row0 + m0 + mt*16 + (lane >> 2);
        #pragma unroll
        for (int nt = 0; nt < 2; nt++) {
            int col = ncol + nw + nt*8 + (lane & 3)*2;
            #pragma unroll
            for (int half = 0; half < 2; half++) {
                int rr = r + half*8;
                if (rr >= row_end) continue;
                float a0 = acc1[mt][nt][2*half], a1 = acc1[mt][nt][2*half+1];
                float c0 = acc3[mt][nt][2*half], c1 = acc3[mt][nt][2*half+1];
                float h0 = a0 / (1.f + __expf(-a0)) * c0;
                float h1 = a1 / (1.f + __expf(-a1)) * c1;
                __half b0 = __float2half(h0), b1 = __float2half(h1);
                float l0 = h0 - __half2float(b0), l1 = h1 - __half2float(b1);
                unsigned hv = (unsigned)__half_as_ushort(b0) | ((unsigned)__half_as_ushort(b1) << 16);
                unsigned lv = (unsigned)__half_as_ushort(__float2half(l0))
                            | ((unsigned)__half_as_ushort(__float2half(l1)) << 16);
                *(unsigned*)(g_Hh + (size_t)rr*FDIM + col) = hv;
                *(unsigned*)(g_Hl + (size_t)rr*FDIM + col) = lv;
            }
        }
    }
}

// ---------------- GEMM2: Og = (H @ W2) * route_weight, fp16 split-2 ----------------
__global__ __launch_bounds__(256, 2) void k_gemm2() {
    int e = g_tile_e[blockIdx.y];
    if (e < 0) return;
    int row0 = g_tile_r[blockIdx.y];
    int row_end = g_offs[e + 1];
    int ncol = blockIdx.x * 64;

    extern __shared__ __align__(128) char sm[];
    unsigned sbase = smem_u32(sm);
    int tid = threadIdx.x, lane = tid & 31, wid = tid >> 5;

    int rowA = tid >> 1, vA = (tid & 1) * 2;
    int ar = row0 + rowA; if (ar > TOTAL-1) ar = TOTAL-1;
    const __half* gAh = g_Hh + (size_t)ar*FDIM + vA*8;
    const __half* gAl = g_Hl + (size_t)ar*FDIM + vA*8;
    unsigned sA0 = SW64(rowA, vA), sA1 = SW64(rowA, vA + 1);

    int rB = tid >> 2, vB = tid & 3;
    size_t eoff = (size_t)e*FDIM*DIM + (size_t)ncol*FDIM;
    const __half* gB = g_W2h + eoff + (size_t)rB*FDIM + vB*8;
    unsigned sB = SW64(rB, vB);

    auto load_stage = [&](int kt) {
        unsigned st = sbase + (kt % 3)*ST2;
        int ko = kt * 32;
        cp16(st + sA0,        gAh + ko);
        cp16(st + sA1,        gAh + ko + 8);
        cp16(st + 8192 + sA0, gAl + ko);
        cp16(st + 8192 + sA1, gAl + ko + 8);
        cp16(st + 16384 + sB, gB + ko);
        CP_COMMIT();
    };

    int m0 = (wid & 1) * 64, nw = (wid >> 1) * 16;
    unsigned aoff[2], boff[2];
    #pragma unroll
    for (int s = 0; s < 2; s++) {
        aoff[s] = SW64(m0 + (lane & 15), 2*s + (lane >> 4));
        boff[s] = SW64(nw + (lane & 15), 2*s + (lane >> 4));
    }

    float acc[4][2][4] = {};

    load_stage(0);
    load_stage(1);

    const int NKT = FDIM / 32;  // 128
    for (int kt = 0; kt < NKT; kt++) {
        if (kt < NKT-1) CP_WAIT1(); else CP_WAIT0();
        __syncthreads();
        if (kt + 2 < NKT) load_stage(kt + 2);

        unsigned st = sbase + (kt % 3)*ST2;
        #pragma unroll
        for (int s = 0; s < 2; s++) {
            unsigned tbh[4];
            ldsm4(tbh, st + 16384 + boff[s]);
            #pragma unroll
            for (int mt = 0; mt < 4; mt++) {
                unsigned ah[4], al[4];
                ldsm4(ah, st + aoff[s] + mt*1024);
                ldsm4(al, st + 8192 + aoff[s] + mt*1024);
                #pragma unroll
                for (int nt = 0; nt < 2; nt++) {
                    mma16816(acc[mt][nt], ah, tbh[nt], tbh[nt+2]);
                    mma16816(acc[mt][nt], al, tbh[nt], tbh[nt+2]);
                }
            }
        }
        __syncthreads();
    }

    #pragma unroll
    for (int mt = 0; mt < 4; mt++) {
        int r = row0 + m0 + mt*16 + (lane >> 2);
        #pragma unroll
        for (int nt = 0; nt < 2; nt++) {
            int col = ncol + nw + nt*8 + (lane & 3)*2;
            #pragma unroll
            for (int half = 0; half < 2; half++) {
                int rr = r + half*8;
                if (rr >= row_end) continue;
                float wg = g_wgt[rr];
                *(float2*)(g_Og + (size_t)rr*DIM + col) =
                    make_float2(acc[mt][nt][2*half]*wg, acc[mt][nt][2*half+1]*wg);
            }
        }
    }
}

// ---------------- combine ----------------
__global__ void k_combine(float* __restrict__ out) {
    int t = blockIdx.x;
    int s0 = g_slot[2*t], s1 = g_slot[2*t+1];
    float4 a = ((const float4*)(g_Og + (size_t)s0 * DIM))[threadIdx.x];
    float4 b = ((const float4*)(g_Og + (size_t)s1 * DIM))[threadIdx.x];
    ((float4*)(out + (size_t)t * DIM))[threadIdx.x] =
        make_float4(a.x + b.x, a.y + b.y, a.z + b.z, a.w + b.w);
}

// ---------------- launch ----------------
extern "C" void kernel_launch(void* const* d_in, const int* in_sizes, int n_in,
                              void* d_out, int out_size) {
    const float* x  = (const float*)d_in[0];
    const float* gw = (const float*)d_in[1];
    const float* w1 = (const float*)d_in[2];
    const float* w2 = (const float*)d_in[3];
    const float* w3 = (const float*)d_in[4];
    float* out = (float*)d_out;

    cudaFuncSetAttribute(k_gemm1, cudaFuncAttributeMaxDynamicSharedMemorySize, 3*ST1);
    cudaFuncSetAttribute(k_gemm2, cudaFuncAttributeMaxDynamicSharedMemorySize, 3*ST2);

    k_zero<<<1, 32>>>();
    k_gate<<<T_TOK / 8, 256>>>(x, gw);
    k_scan<<<1, 32>>>();
    k_scatter<<<TOTAL / 256, 256>>>();
    k_gather<<<TOTAL, 256>>>(x);
    k_wsplit<<<dim3(FDIM/32, DIM/32, NEXP), dim3(32, 8)>>>(w1, 0, DIM, FDIM);
    k_wsplit<<<dim3(FDIM/32, DIM/32, NEXP), dim3(32, 8)>>>(w3, 1, DIM, FDIM);
    k_wsplit<<<dim3(DIM/32, FDIM/32, NEXP), dim3(32, 8)>>>(w2, 2, FDIM, DIM);
    k_gemm1<<<dim3(FDIM/64, MAX_TILES), 256, 3*ST1>>>();   // 64 x 136
    k_gemm2<<<dim3(DIM/64,  MAX_TILES), 256, 3*ST2>>>();   // 16 x 136
    k_combine<<<T_TOK, 256>>>(out);
}

// round 17
// speedup vs baseline: 2.9451x; 1.0470x over previous
#include <cuda_runtime.h>
#include <cuda_fp16.h>
#include <math.h>

// ---------------- problem constants ----------------
#define T_TOK 8192
#define DIM   1024
#define FDIM  4096
#define NEXP  8
#define TOTAL (T_TOK*2)               // 16384 routed rows (exact invariant)
#define BM 128
#define MAX_TILES (TOTAL/BM + NEXP)   // 136

// fp16 split-2 (A hi/lo, B hi only), BK=32, 64B-pitch swizzled rows, 4-stage cp.async
// GEMM1 stage: Xh,Xl 128x64B + W1h,W3h 64x64B  = 24576
// GEMM2 stage: Hh,Hl 128x64B + W2h 128x64B     = 24576
#define ST1 24576
#define ST2 24576

// ---------------- device scratch ----------------
__device__ __align__(16) __half g_Xh[(size_t)TOTAL*DIM];
__device__ __align__(16) __half g_Xl[(size_t)TOTAL*DIM];
__device__ __align__(16) __half g_Hh[(size_t)TOTAL*FDIM];
__device__ __align__(16) __half g_Hl[(size_t)TOTAL*FDIM];
__device__ __align__(16) __half g_W1h[(size_t)NEXP*DIM*FDIM];
__device__ __align__(16) __half g_W3h[(size_t)NEXP*DIM*FDIM];
__device__ __align__(16) __half g_W2h[(size_t)NEXP*FDIM*DIM];
__device__ __align__(16) float g_Og[(size_t)TOTAL*DIM];
__device__ int   g_tok[TOTAL];
__device__ float g_wgt[TOTAL];
__device__ int   g_slot[TOTAL];
__device__ int   g_topk_idx[TOTAL];
__device__ float g_topk_w[TOTAL];
__device__ int   g_counts[NEXP];
__device__ int   g_offs[NEXP+1];
__device__ int   g_cursor[NEXP];
__device__ int   g_tile_e[MAX_TILES];
__device__ int   g_tile_r[MAX_TILES];

// ---------------- PTX helpers (sm_80-class only) ----------------
__device__ __forceinline__ unsigned smem_u32(const void* p) {
    unsigned a;
    asm("{ .reg .u64 t; cvta.to.shared.u64 t, %1; cvt.u32.u64 %0, t; }" : "=r"(a) : "l"(p));
    return a;
}
__device__ __forceinline__ void cp16(unsigned dst, const void* src) {
    asm volatile("cp.async.cg.shared.global [%0], [%1], 16;" :: "r"(dst), "l"(src) : "memory");
}
#define CP_COMMIT() asm volatile("cp.async.commit_group;" ::: "memory")
#define CP_WAIT2()  asm volatile("cp.async.wait_group 2;" ::: "memory")

// 64B-pitch row swizzle: row r, 16B-vec v(0..3): quad(r,v)=(4r+(v^((r>>1)&3)))%8
// hits all 8 bank-quads in every ldmatrix 8-row phase (verified r=0..7 x v=0..3).
#define SW64(r, v) ((unsigned)(r)*64u + ((((unsigned)(v)) ^ (((unsigned)(r)>>1)&3u))&3u)*16u)

__device__ __forceinline__ void ldsm4(unsigned r[4], unsigned addr) {
    asm volatile("ldmatrix.sync.aligned.m8n8.x4.shared.b16 {%0,%1,%2,%3}, [%4];"
                 : "=r"(r[0]), "=r"(r[1]), "=r"(r[2]), "=r"(r[3]) : "r"(addr));
}
__device__ __forceinline__ void mma16816(float d[4], const unsigned a[4], unsigned b0, unsigned b1) {
    asm volatile("mma.sync.aligned.m16n8k16.row.col.f32.f16.f16.f32 "
                 "{%0,%1,%2,%3}, {%4,%5,%6,%7}, {%8,%9}, {%0,%1,%2,%3};"
                 : "+f"(d[0]), "+f"(d[1]), "+f"(d[2]), "+f"(d[3])
                 : "r"(a[0]), "r"(a[1]), "r"(a[2]), "r"(a[3]), "r"(b0), "r"(b1));
}

// ---------------- routing kernels (proven) ----------------
__global__ void k_zero() { if (threadIdx.x < NEXP) g_counts[threadIdx.x] = 0; }

__global__ void k_gate(const float* __restrict__ x, const float* __restrict__ gw) {
    int warp = threadIdx.x >> 5, lane = threadIdx.x & 31;
    int t = blockIdx.x * 8 + warp;
    const float* xr = x + (size_t)t * DIM;
    float acc[NEXP];
    #pragma unroll
    for (int e = 0; e < NEXP; e++) acc[e] = 0.f;
    #pragma unroll 4
    for (int it = 0; it < DIM/32; it++) {
        int d = it*32 + lane;
        float xv = xr[d];
        const float4* g4 = (const float4*)(gw + (size_t)d * NEXP);
        float4 ga = g4[0], gb = g4[1];
        acc[0] += xv*ga.x; acc[1] += xv*ga.y; acc[2] += xv*ga.z; acc[3] += xv*ga.w;
        acc[4] += xv*gb.x; acc[5] += xv*gb.y; acc[6] += xv*gb.z; acc[7] += xv*gb.w;
    }
    #pragma unroll
    for (int e = 0; e < NEXP; e++)
        #pragma unroll
        for (int off = 16; off > 0; off >>= 1)
            acc[e] += __shfl_xor_sync(0xffffffffu, acc[e], off);
    if (lane == 0) {
        float v0 = -INFINITY, v1 = -INFINITY; int i0 = 0, i1 = 0;
        #pragma unroll
        for (int e = 0; e < NEXP; e++) {
            float s = acc[e];
            if (s > v0)      { v1 = v0; i1 = i0; v0 = s; i0 = e; }
            else if (s > v1) { v1 = s;  i1 = e; }
        }
        float e1 = expf(v1 - v0);
        float inv = 1.f / (1.f + e1);
        g_topk_idx[2*t]   = i0; g_topk_w[2*t]   = inv;
        g_topk_idx[2*t+1] = i1; g_topk_w[2*t+1] = e1 * inv;
        atomicAdd(&g_counts[i0], 1);
        atomicAdd(&g_counts[i1], 1);
    }
}

__global__ void k_scan() {
    if (threadIdx.x != 0) return;
    int off = 0;
    for (int e = 0; e < NEXP; e++) { g_offs[e] = off; g_cursor[e] = off; off += g_counts[e]; }
    g_offs[NEXP] = off;
    int tc = 0;
    for (int e = 0; e < NEXP; e++)
        for (int r = 0; r < g_counts[e]; r += BM) { g_tile_e[tc] = e; g_tile_r[tc] = g_offs[e] + r; tc++; }
    for (; tc < MAX_TILES; tc++) g_tile_e[tc] = -1;
}

__global__ void k_scatter() {
    int i = blockIdx.x * blockDim.x + threadIdx.x;
    if (i >= TOTAL) return;
    int e = g_topk_idx[i];
    int p = atomicAdd(&g_cursor[e], 1);
    g_tok[p] = i >> 1; g_wgt[p] = g_topk_w[i]; g_slot[i] = p;
}

// gather + split to fp16 hi/lo
__global__ void k_gather(const float* __restrict__ x) {
    int p = blockIdx.x, t = g_tok[p];
    float4 v = ((const float4*)(x + (size_t)t * DIM))[threadIdx.x];
    float f[4] = {v.x, v.y, v.z, v.w};
    unsigned hs[4], ls[4];
    #pragma unroll
    for (int i = 0; i < 4; i++) {
        __half h = __float2half(f[i]);
        float lo = f[i] - __half2float(h);
        hs[i] = __half_as_ushort(h);
        ls[i] = __half_as_ushort(__float2half(lo));
    }
    ((uint2*)(g_Xh + (size_t)p * DIM))[threadIdx.x] = make_uint2(hs[0]|(hs[1]<<16), hs[2]|(hs[3]<<16));
    ((uint2*)(g_Xl + (size_t)p * DIM))[threadIdx.x] = make_uint2(ls[0]|(ls[1]<<16), ls[2]|(ls[3]<<16));
}

// transpose + convert weights: W[R][C] fp32 -> [C][R] fp16 (hi only).
// Outputs selected INSIDE device code (ATS-bug fix, R11-proven).
__global__ void k_wsplit(const float* __restrict__ W, int sel, int R, int C) {
    __half* oh;
    if      (sel == 0) oh = g_W1h;
    else if (sel == 1) oh = g_W3h;
    else               oh = g_W2h;
    __shared__ float tb[32][33];
    const float* Wb = W + (size_t)blockIdx.z * R * C;
    size_t ob = (size_t)blockIdx.z * R * C;
    int tx = threadIdx.x, ty = threadIdx.y;
    #pragma unroll
    for (int i = 0; i < 4; i++) {
        int r = blockIdx.y*32 + ty + i*8;
        tb[ty + i*8][tx] = Wb[(size_t)r * C + blockIdx.x*32 + tx];
    }
    __syncthreads();
    int rr = blockIdx.y*32 + tx;
    #pragma unroll
    for (int i = 0; i < 4; i++) {
        int cc = blockIdx.x*32 + ty + i*8;
        oh[ob + (size_t)cc * R + rr] = __float2half(tb[tx][ty + i*8]);
    }
}

// ---------------- GEMM1 (fused SwiGLU): H = silu(X@W1)*(X@W3), fp16 split-2 ----------------
// CTA 128(M) x 64(N), BK=32 (2 x k16), 256 thr, 8 warps (2M x 4N), warp 64x16.
// 4-stage cp.async, ONE barrier per k-iter.
__global__ __launch_bounds__(256, 2) void k_gemm1() {
    int e = g_tile_e[blockIdx.y];
    if (e < 0) return;
    int row0 = g_tile_r[blockIdx.y];
    int row_end = g_offs[e + 1];
    int ncol = blockIdx.x * 64;

    extern __shared__ __align__(128) char sm[];
    unsigned sbase = smem_u32(sm);
    int tid = threadIdx.x, lane = tid & 31, wid = tid >> 5;

    // ---- cp.async mapping
    int rowA = tid >> 1, vA = (tid & 1) * 2;
    int ar = row0 + rowA; if (ar > TOTAL-1) ar = TOTAL-1;
    const __half* gAh = g_Xh + (size_t)ar*DIM + vA*8;
    const __half* gAl = g_Xl + (size_t)ar*DIM + vA*8;
    unsigned sA0 = SW64(rowA, vA), sA1 = SW64(rowA, vA + 1);
    int rB = tid >> 2, vB = tid & 3;
    size_t eoff = (size_t)e*DIM*FDIM + (size_t)ncol*DIM;
    const __half* gB1 = g_W1h + eoff + (size_t)rB*DIM + vB*8;
    const __half* gB3 = g_W3h + eoff + (size_t)rB*DIM + vB*8;
    unsigned sB = SW64(rB, vB);

    auto load_stage = [&](int kt) {
        unsigned st = sbase + (kt & 3)*ST1;
        int ko = kt * 32;
        cp16(st + sA0,        gAh + ko);
        cp16(st + sA1,        gAh + ko + 8);
        cp16(st + 8192 + sA0, gAl + ko);
        cp16(st + 8192 + sA1, gAl + ko + 8);
        cp16(st + 16384 + sB, gB1 + ko);
        cp16(st + 20480 + sB, gB3 + ko);
        CP_COMMIT();
    };

    // ---- compute mapping (per k16 sub-step s: vec = 2s + (lane>>4))
    int m0 = (wid & 1) * 64, nw = (wid >> 1) * 16;
    unsigned aoff[2], boff[2];
    #pragma unroll
    for (int s = 0; s < 2; s++) {
        aoff[s] = SW64(m0 + (lane & 15), 2*s + (lane >> 4));
        boff[s] = SW64(nw + (lane & 15), 2*s + (lane >> 4));
    }

    float acc1[4][2][4] = {}, acc3[4][2][4] = {};

    load_stage(0);
    load_stage(1);
    load_stage(2);

    const int NKT = DIM / 32;   // 32
    for (int kt = 0; kt < NKT; kt++) {
        CP_WAIT2();
        __syncthreads();
        if (kt + 3 < NKT) load_stage(kt + 3); else CP_COMMIT();

        unsigned st = sbase + (kt & 3)*ST1;
        #pragma unroll
        for (int s = 0; s < 2; s++) {
            unsigned t1h[4], t3h[4];
            ldsm4(t1h, st + 16384 + boff[s]);
            ldsm4(t3h, st + 20480 + boff[s]);
            #pragma unroll
            for (int mt = 0; mt < 4; mt++) {
                unsigned ah[4], al[4];
                ldsm4(ah, st + aoff[s] + mt*1024);
                ldsm4(al, st + 8192 + aoff[s] + mt*1024);
                #pragma unroll
                for (int nt = 0; nt < 2; nt++) {
                    mma16816(acc1[mt][nt], ah, t1h[nt], t1h[nt+2]);
                    mma16816(acc1[mt][nt], al, t1h[nt], t1h[nt+2]);
                    mma16816(acc3[mt][nt], ah, t3h[nt], t3h[nt+2]);
                    mma16816(acc3[mt][nt], al, t3h[nt], t3h[nt+2]);
                }
            }
        }
    }

    // epilogue: SwiGLU -> Hh/Hl (fp16 hi/lo)
    #pragma unroll
    for (int mt = 0; mt < 4; mt++) {
        int r = row0 + m0 + mt*16 + (lane >> 2);
        #pragma unroll
        for (int nt = 0; nt < 2; nt++) {
            int col = ncol + nw + nt*8 + (lane & 3)*2;
            #pragma unroll
            for (int half = 0; half < 2; half++) {
                int rr = r + half*8;
                if (rr >= row_end) continue;
                float a0 = acc1[mt][nt][2*half], a1 = acc1[mt][nt][2*half+1];
                float c0 = acc3[mt][nt][2*half], c1 = acc3[mt][nt][2*half+1];
                float h0 = a0 / (1.f + __expf(-a0)) * c0;
                float h1 = a1 / (1.f + __expf(-a1)) * c1;
                __half b0 = __float2half(h0), b1 = __float2half(h1);
                float l0 = h0 - __half2float(b0), l1 = h1 - __half2float(b1);
                unsigned hv = (unsigned)__half_as_ushort(b0) | ((unsigned)__half_as_ushort(b1) << 16);
                unsigned lv = (unsigned)__half_as_ushort(__float2half(l0))
                            | ((unsigned)__half_as_ushort(__float2half(l1)) << 16);
                *(unsigned*)(g_Hh + (size_t)rr*FDIM + col) = hv;
                *(unsigned*)(g_Hl + (size_t)rr*FDIM + col) = lv;
            }
        }
    }
}

// ---------------- GEMM2: Og = (H @ W2) * route_weight, fp16 split-2 ----------------
// CTA 128(M) x 128(N), BK=32, 256 thr, 8 warps (2M x 2N), warp 64x32 (nt=4).
// 4-stage cp.async, ONE barrier per k-iter.
__global__ __launch_bounds__(256, 2) void k_gemm2() {
    int e = g_tile_e[blockIdx.y];
    if (e < 0) return;
    int row0 = g_tile_r[blockIdx.y];
    int row_end = g_offs[e + 1];
    int ncol = blockIdx.x * 128;

    extern __shared__ __align__(128) char sm[];
    unsigned sbase = smem_u32(sm);
    int tid = threadIdx.x, lane = tid & 31, wid = tid >> 5;

    int rowA = tid >> 1, vA = (tid & 1) * 2;
    int ar = row0 + rowA; if (ar > TOTAL-1) ar = TOTAL-1;
    const __half* gAh = g_Hh + (size_t)ar*FDIM + vA*8;
    const __half* gAl = g_Hl + (size_t)ar*FDIM + vA*8;
    unsigned sA0 = SW64(rowA, vA), sA1 = SW64(rowA, vA + 1);

    // B: 128 rows x 4 vecs (2 per thread)
    int rB = tid >> 1, vB = (tid & 1) * 2;
    size_t eoff = (size_t)e*FDIM*DIM + (size_t)ncol*FDIM;
    const __half* gB = g_W2h + eoff + (size_t)rB*FDIM + vB*8;
    unsigned sB0 = SW64(rB, vB), sB1 = SW64(rB, vB + 1);

    auto load_stage = [&](int kt) {
        unsigned st = sbase + (kt & 3)*ST2;
        int ko = kt * 32;
        cp16(st + sA0,         gAh + ko);
        cp16(st + sA1,         gAh + ko + 8);
        cp16(st + 8192 + sA0,  gAl + ko);
        cp16(st + 8192 + sA1,  gAl + ko + 8);
        cp16(st + 16384 + sB0, gB + ko);
        cp16(st + 16384 + sB1, gB + ko + 8);
        CP_COMMIT();
    };

    int m0 = (wid & 1) * 64, nw0 = (wid >> 1) * 32;
    unsigned aoff[2], boff[2][2];
    #pragma unroll
    for (int s = 0; s < 2; s++) {
        aoff[s] = SW64(m0 + (lane & 15), 2*s + (lane >> 4));
        #pragma unroll
        for (int j = 0; j < 2; j++)
            boff[s][j] = SW64(nw0 + j*16 + (lane & 15), 2*s + (lane >> 4));
    }

    float acc[4][4][4] = {};

    load_stage(0);
    load_stage(1);
    load_stage(2);

    const int NKT = FDIM / 32;  // 128
    for (int kt = 0; kt < NKT; kt++) {
        CP_WAIT2();
        __syncthreads();
        if (kt + 3 < NKT) load_stage(kt + 3); else CP_COMMIT();

        unsigned st = sbase + (kt & 3)*ST2;
        #pragma unroll
        for (int s = 0; s < 2; s++) {
            unsigned tb0[4], tb1[4];
            ldsm4(tb0, st + 16384 + boff[s][0]);
            ldsm4(tb1, st + 16384 + boff[s][1]);
            #pragma unroll
            for (int mt = 0; mt < 4; mt++) {
                unsigned ah[4], al[4];
                ldsm4(ah, st + aoff[s] + mt*1024);
                ldsm4(al, st + 8192 + aoff[s] + mt*1024);
                #pragma unroll
                for (int ntl = 0; ntl < 2; ntl++) {
                    mma16816(acc[mt][ntl],   ah, tb0[ntl], tb0[ntl+2]);
                    mma16816(acc[mt][ntl],   al, tb0[ntl], tb0[ntl+2]);
                    mma16816(acc[mt][2+ntl], ah, tb1[ntl], tb1[ntl+2]);
                    mma16816(acc[mt][2+ntl], al, tb1[ntl], tb1[ntl+2]);
                }
            }
        }
    }

    #pragma unroll
    for (int mt = 0; mt < 4; mt++) {
        int r = row0 + m0 + mt*16 + (lane >> 2);
        #pragma unroll
        for (int j = 0; j < 2; j++)
        #pragma unroll
        for (int ntl = 0; ntl < 2; ntl++) {
            int col = ncol + nw0 + j*16 + ntl*8 + (lane & 3)*2;
            int nt = j*2 + ntl;
            #pragma unroll
            for (int half = 0; half < 2; half++) {
                int rr = r + half*8;
                if (rr >= row_end) continue;
                float wg = g_wgt[rr];
                *(float2*)(g_Og + (size_t)rr*DIM + col) =
                    make_float2(acc[mt][nt][2*half]*wg, acc[mt][nt][2*half+1]*wg);
            }
        }
    }
}

// ---------------- combine ----------------
__global__ void k_combine(float* __restrict__ out) {
    int t = blockIdx.x;
    int s0 = g_slot[2*t], s1 = g_slot[2*t+1];
    float4 a = ((const float4*)(g_Og + (size_t)s0 * DIM))[threadIdx.x];
    float4 b = ((const float4*)(g_Og + (size_t)s1 * DIM))[threadIdx.x];
    ((float4*)(out + (size_t)t * DIM))[threadIdx.x] =
        make_float4(a.x + b.x, a.y + b.y, a.z + b.z, a.w + b.w);
}

// ---------------- launch ----------------
extern "C" void kernel_launch(void* const* d_in, const int* in_sizes, int n_in,
                              void* d_out, int out_size) {
    const float* x  = (const float*)d_in[0];
    const float* gw = (const float*)d_in[1];
    const float* w1 = (const float*)d_in[2];
    const float* w2 = (const float*)d_in[3];
    const float* w3 = (const float*)d_in[4];
    float* out = (float*)d_out;

    cudaFuncSetAttribute(k_gemm1, cudaFuncAttributeMaxDynamicSharedMemorySize, 4*ST1);
    cudaFuncSetAttribute(k_gemm2, cudaFuncAttributeMaxDynamicSharedMemorySize, 4*ST2);

    k_zero<<<1, 32>>>();
    k_gate<<<T_TOK / 8, 256>>>(x, gw);
    k_scan<<<1, 32>>>();
    k_scatter<<<TOTAL / 256, 256>>>();
    k_gather<<<TOTAL, 256>>>(x);
    k_wsplit<<<dim3(FDIM/32, DIM/32, NEXP), dim3(32, 8)>>>(w1, 0, DIM, FDIM);
    k_wsplit<<<dim3(FDIM/32, DIM/32, NEXP), dim3(32, 8)>>>(w3, 1, DIM, FDIM);
    k_wsplit<<<dim3(DIM/32, FDIM/32, NEXP), dim3(32, 8)>>>(w2, 2, FDIM, DIM);
    k_gemm1<<<dim3(FDIM/64, MAX_TILES), 256, 4*ST1>>>();   // 64 x 136
    k_gemm2<<<dim3(DIM/128, MAX_TILES), 256, 4*ST2>>>();   // 8 x 136
    k_combine<<<T_TOK, 256>>>(out);
}